// round 2
// baseline (speedup 1.0000x reference)
#include <cuda_runtime.h>

#define Bb 4
#define Ss 1024
#define Dd 512
#define Hh 8
#define DH 64
#define RR (2*Ss-1)   // 2047

// ---------------- scratch (device globals; no allocation) ----------------
__device__ float g_q[Bb*Hh*Ss*DH];     // [b][h][s][d]
__device__ float g_k[Bb*Hh*Ss*DH];
__device__ float g_v[Bb*Hh*Ss*DH];
__device__ float g_rel[RR*DH];         // [r][d]
__device__ float g_ctx[Bb*Ss*Dd];      // [b][s][h*64+d]

// ---------------- projection GEMM: C = A @ W^T + bias --------------------
// A: [4096, 512] row-major, W: [512, 512] row-major (we need W[n][k])
// MODE 0: permuted store to [B,H,S,DH]; MODE 1: plain [M,N]
template<int MODE>
__global__ __launch_bounds__(256)
void proj_gemm(const float* __restrict__ A, const float* __restrict__ W,
               const float* __restrict__ bias, float* __restrict__ out) {
    const int K = 512;
    __shared__ float As[16][128];   // [k][m]
    __shared__ float Ws[16][64];    // [k][n]
    int tid = threadIdx.x;
    int tx = tid & 15, ty = tid >> 4;
    int m0 = blockIdx.y * 128;
    int n0 = blockIdx.x * 64;

    float acc[8][4];
    #pragma unroll
    for (int i = 0; i < 8; i++)
        #pragma unroll
        for (int j = 0; j < 4; j++) acc[i][j] = 0.f;

    for (int k0 = 0; k0 < K; k0 += 16) {
        #pragma unroll
        for (int l = 0; l < 2; l++) {
            int v = tid + l * 256;              // 512 float4 = 128 rows x 4
            int m = v >> 2, k4 = (v & 3) * 4;
            float4 a = *reinterpret_cast<const float4*>(&A[(size_t)(m0 + m) * K + k0 + k4]);
            As[k4 + 0][m] = a.x; As[k4 + 1][m] = a.y;
            As[k4 + 2][m] = a.z; As[k4 + 3][m] = a.w;
        }
        {
            int n = tid >> 2, k4 = (tid & 3) * 4;
            float4 w = *reinterpret_cast<const float4*>(&W[(size_t)(n0 + n) * K + k0 + k4]);
            Ws[k4 + 0][n] = w.x; Ws[k4 + 1][n] = w.y;
            Ws[k4 + 2][n] = w.z; Ws[k4 + 3][n] = w.w;
        }
        __syncthreads();
        #pragma unroll
        for (int k = 0; k < 16; k++) {
            float am[8], wn[4];
            #pragma unroll
            for (int i = 0; i < 8; i++) am[i] = As[k][ty * 8 + i];
            #pragma unroll
            for (int j = 0; j < 4; j++) wn[j] = Ws[k][tx * 4 + j];
            #pragma unroll
            for (int i = 0; i < 8; i++)
                #pragma unroll
                for (int j = 0; j < 4; j++) acc[i][j] += am[i] * wn[j];
        }
        __syncthreads();
    }

    int nb = n0 + tx * 4;
    float4 bv = *reinterpret_cast<const float4*>(&bias[nb]);
    #pragma unroll
    for (int i = 0; i < 8; i++) {
        int m = m0 + ty * 8 + i;
        float4 r;
        r.x = acc[i][0] + bv.x; r.y = acc[i][1] + bv.y;
        r.z = acc[i][2] + bv.z; r.w = acc[i][3] + bv.w;
        if (MODE == 0) {
            int b = m >> 10, s = m & 1023;
            int h = nb >> 6, d = nb & 63;
            *reinterpret_cast<float4*>(&out[(size_t)(((b * Hh + h) << 10) | s) * DH + d]) = r;
        } else {
            *reinterpret_cast<float4*>(&out[(size_t)m * Dd + nb]) = r;
        }
    }
}

// ---------------- rel projection: rel = pos_emb @ Wp^T + bp --------------
__global__ __launch_bounds__(64)
void rel_proj_kernel(const float* __restrict__ P, const float* __restrict__ Wp,
                     const float* __restrict__ bp, float* __restrict__ out) {
    __shared__ float row[64];
    int r = blockIdx.x;
    int d = threadIdx.x;
    row[d] = P[r * 64 + d];
    __syncthreads();
    float acc = bp[d];
    #pragma unroll 16
    for (int c = 0; c < 64; c++) acc += row[c] * Wp[d * 64 + c];
    out[r * 64 + d] = acc;
}

// ---------------- fused content + (pre-shifted) pos scores ---------------
// content[s,t] = q[s].k[t]; pos[s,t] = q[s].rel[t-s+1023]  (always in-range)
extern __shared__ float sc_smem[];
__global__ __launch_bounds__(256)
void scores_kernel(const float* __restrict__ q, const float* __restrict__ k,
                   const float* __restrict__ rel,
                   float* __restrict__ c_out, float* __restrict__ p_out) {
    float* qsT = sc_smem;            // [64 d][65]
    float* ksT = qsT + 64 * 65;      // [64 d][65]
    float* rsT = ksT + 64 * 65;      // [64 d][129] (127 used)

    int bh = blockIdx.z;
    int s0 = blockIdx.y * 64;
    int t0 = blockIdx.x * 64;
    const float* qb = q + (size_t)bh * Ss * DH;
    const float* kb = k + (size_t)bh * Ss * DH;
    int rbase = t0 - s0 + (Ss - 1) - 63;   // in [0, 1920]
    int tid = threadIdx.x;

    for (int idx = tid; idx < 64 * 64; idx += 256) {
        int s = idx >> 6, d = idx & 63;
        qsT[d * 65 + s] = qb[(s0 + s) * 64 + d];
        ksT[d * 65 + s] = kb[(t0 + s) * 64 + d];
    }
    for (int idx = tid; idx < 127 * 64; idx += 256) {
        int li = idx >> 6, d = idx & 63;
        rsT[d * 129 + li] = rel[(rbase + li) * 64 + d];
    }
    __syncthreads();

    int tx = tid & 15, ty = tid >> 4;
    int si0 = ty * 4, tj0 = tx * 4;
    int tb = tj0 - si0 + 60;               // window base: li = tb + (j - i + 3)

    float cacc[4][4] = {}, pacc[4][4] = {};
    for (int d = 0; d < 64; d++) {
        float qv[4], kv[4], rv[7];
        const float* qrow = &qsT[d * 65 + si0];
        const float* krow = &ksT[d * 65 + tj0];
        const float* rrow = &rsT[d * 129 + tb];
        #pragma unroll
        for (int i = 0; i < 4; i++) qv[i] = qrow[i];
        #pragma unroll
        for (int j = 0; j < 4; j++) kv[j] = krow[j];
        #pragma unroll
        for (int u = 0; u < 7; u++) rv[u] = rrow[u];
        #pragma unroll
        for (int i = 0; i < 4; i++)
            #pragma unroll
            for (int j = 0; j < 4; j++) {
                cacc[i][j] += qv[i] * kv[j];
                pacc[i][j] += qv[i] * rv[j - i + 3];
            }
    }

    #pragma unroll
    for (int i = 0; i < 4; i++) {
        int s = s0 + si0 + i;
        size_t off = ((size_t)bh * Ss + s) * Ss + t0 + tj0;
        float4 cv = make_float4(cacc[i][0], cacc[i][1], cacc[i][2], cacc[i][3]);
        float4 pv = make_float4(pacc[i][0], pacc[i][1], pacc[i][2], pacc[i][3]);
        *reinterpret_cast<float4*>(&c_out[off]) = cv;
        *reinterpret_cast<float4*>(&p_out[off]) = pv;
    }
}

// ---------------- row softmax over (content+pos)/sqrt(512) ---------------
__global__ __launch_bounds__(256)
void softmax_kernel(const float* __restrict__ c, const float* __restrict__ p,
                    float* __restrict__ attn) {
    const float scl = 0.04419417382415922f;   // 1/sqrt(512)
    size_t base = (size_t)blockIdx.x * Ss;
    int tid = threadIdx.x;
    float4 cv = *reinterpret_cast<const float4*>(&c[base + tid * 4]);
    float4 pv = *reinterpret_cast<const float4*>(&p[base + tid * 4]);
    float s0 = (cv.x + pv.x) * scl, s1 = (cv.y + pv.y) * scl;
    float s2 = (cv.z + pv.z) * scl, s3 = (cv.w + pv.w) * scl;

    float m = fmaxf(fmaxf(s0, s1), fmaxf(s2, s3));
    #pragma unroll
    for (int o = 16; o; o >>= 1) m = fmaxf(m, __shfl_xor_sync(0xffffffffu, m, o));
    __shared__ float red[8];
    int wid = tid >> 5, lid = tid & 31;
    if (lid == 0) red[wid] = m;
    __syncthreads();
    m = red[0];
    #pragma unroll
    for (int w = 1; w < 8; w++) m = fmaxf(m, red[w]);

    float e0 = __expf(s0 - m), e1 = __expf(s1 - m);
    float e2 = __expf(s2 - m), e3 = __expf(s3 - m);
    float sum = (e0 + e1) + (e2 + e3);
    #pragma unroll
    for (int o = 16; o; o >>= 1) sum += __shfl_xor_sync(0xffffffffu, sum, o);
    __syncthreads();                 // red reads done before rewrite
    if (lid == 0) red[wid] = sum;
    __syncthreads();
    float tot = red[0];
    #pragma unroll
    for (int w = 1; w < 8; w++) tot += red[w];
    float inv = 1.0f / tot;

    float4 r = make_float4(e0 * inv, e1 * inv, e2 * inv, e3 * inv);
    *reinterpret_cast<float4*>(&attn[base + tid * 4]) = r;
}

// ---------------- ctx = attn @ v, stored as [B,S,D] ----------------------
__global__ __launch_bounds__(256)
void ctx_kernel(const float* __restrict__ attn, const float* __restrict__ v,
                float* __restrict__ ctx) {
    __shared__ float AsT[32][65];   // [t][s]
    __shared__ float Vs[32][65];    // [t][d]
    int bh = blockIdx.y;
    int s0 = blockIdx.x * 64;
    const float* ab = attn + (size_t)bh * Ss * Ss;
    const float* vb = v + (size_t)bh * Ss * DH;
    int tid = threadIdx.x, tx = tid & 15, ty = tid >> 4;

    float acc[4][4] = {};
    for (int t0 = 0; t0 < Ss; t0 += 32) {
        for (int idx = tid; idx < 64 * 32; idx += 256) {
            int s = idx >> 5, t = idx & 31;
            AsT[t][s] = ab[(size_t)(s0 + s) * Ss + t0 + t];
        }
        for (int idx = tid; idx < 32 * 64; idx += 256) {
            int t = idx >> 6, d = idx & 63;
            Vs[t][d] = vb[(t0 + t) * 64 + d];
        }
        __syncthreads();
        #pragma unroll
        for (int kk = 0; kk < 32; kk++) {
            float av[4], vv[4];
            #pragma unroll
            for (int i = 0; i < 4; i++) av[i] = AsT[kk][ty * 4 + i];
            #pragma unroll
            for (int j = 0; j < 4; j++) vv[j] = Vs[kk][tx * 4 + j];
            #pragma unroll
            for (int i = 0; i < 4; i++)
                #pragma unroll
                for (int j = 0; j < 4; j++) acc[i][j] += av[i] * vv[j];
        }
        __syncthreads();
    }

    int b = bh >> 3, h = bh & 7;
    #pragma unroll
    for (int i = 0; i < 4; i++) {
        int s = s0 + ty * 4 + i;
        float4 r = make_float4(acc[i][0], acc[i][1], acc[i][2], acc[i][3]);
        *reinterpret_cast<float4*>(&ctx[(size_t)((b << 10) + s) * Dd + (h << 6) + tx * 4]) = r;
    }
}

// -------------------------------------------------------------------------
extern "C" void kernel_launch(void* const* d_in, const int* in_sizes, int n_in,
                              void* d_out, int out_size) {
    const float* query   = (const float*)d_in[0];
    const float* key     = (const float*)d_in[1];
    const float* value   = (const float*)d_in[2];
    const float* pos_emb = (const float*)d_in[3];
    const float* Wq = (const float*)d_in[4];
    const float* bq = (const float*)d_in[5];
    const float* Wk = (const float*)d_in[6];
    const float* bk = (const float*)d_in[7];
    const float* Wv = (const float*)d_in[8];
    const float* bv = (const float*)d_in[9];
    const float* Wo = (const float*)d_in[10];
    const float* bo = (const float*)d_in[11];
    const float* Wp = (const float*)d_in[12];
    const float* bp = (const float*)d_in[13];

    float* out  = (float*)d_out;                       // [B,S,D]
    float* attn = out  + (size_t)Bb * Ss * Dd;         // [B,H,S,S]
    float* csc  = attn + (size_t)Bb * Hh * Ss * Ss;    // content_score
    float* psc  = csc  + (size_t)Bb * Hh * Ss * Ss;    // pos_score (shifted)

    float *qp, *kp, *vp, *relp, *ctxp;
    cudaGetSymbolAddress((void**)&qp,   g_q);
    cudaGetSymbolAddress((void**)&kp,   g_k);
    cudaGetSymbolAddress((void**)&vp,   g_v);
    cudaGetSymbolAddress((void**)&relp, g_rel);
    cudaGetSymbolAddress((void**)&ctxp, g_ctx);

    proj_gemm<0><<<dim3(8, 32), 256>>>(query, Wq, bq, qp);
    proj_gemm<0><<<dim3(8, 32), 256>>>(key,   Wk, bk, kp);
    proj_gemm<0><<<dim3(8, 32), 256>>>(value, Wv, bv, vp);
    rel_proj_kernel<<<RR, 64>>>(pos_emb, Wp, bp, relp);

    const int SMEM_SCORES = (64 * 65 * 2 + 64 * 129) * (int)sizeof(float);  // 66304 B
    cudaFuncSetAttribute(scores_kernel, cudaFuncAttributeMaxDynamicSharedMemorySize,
                         SMEM_SCORES);
    scores_kernel<<<dim3(16, 16, 32), 256, SMEM_SCORES>>>(qp, kp, relp, csc, psc);

    softmax_kernel<<<Bb * Hh * Ss, 256>>>(csc, psc, attn);
    ctx_kernel<<<dim3(16, 32), 256>>>(attn, vp, ctxp);
    proj_gemm<1><<<dim3(8, 32), 256>>>(ctxp, Wo, bo, out);
}

// round 5
// speedup vs baseline: 2.7301x; 2.7301x over previous
#include <cuda_runtime.h>
#include <cuda_bf16.h>
#include <cstdint>

#define Bb 4
#define Ss 1024
#define Dd 512
#define Hh 8
#define DH 64
#define RR 2047
#define RPAD 2304
#define PW 1152

// ---------------- scratch (device globals; zero-init, no allocation) ------
__device__ __nv_bfloat16 g_inqh[4096*512], g_inql[4096*512];
__device__ __nv_bfloat16 g_inkh[4096*512], g_inkl[4096*512];
__device__ __nv_bfloat16 g_invh[4096*512], g_invl[4096*512];
__device__ __nv_bfloat16 g_wqh[512*512], g_wql[512*512];
__device__ __nv_bfloat16 g_wkh[512*512], g_wkl[512*512];
__device__ __nv_bfloat16 g_wvh[512*512], g_wvl[512*512];
__device__ __nv_bfloat16 g_woh[512*512], g_wol[512*512];
__device__ __nv_bfloat16 g_qh[32*1024*64], g_ql[32*1024*64];
__device__ __nv_bfloat16 g_kh[32*1024*64], g_kl[32*1024*64];
__device__ __nv_bfloat16 g_vh[32*1024*64], g_vl[32*1024*64];
__device__ __nv_bfloat16 g_relh[RPAD*64], g_rell[RPAD*64];   // rows >=2047 stay 0
__device__ float         g_P[32*8*128*PW];                   // 151 MB
__device__ __nv_bfloat16 g_ctxh[4096*512], g_ctxl[4096*512];

extern __shared__ char dsm[];

// ======================= helpers =========================================
__device__ __forceinline__ uint32_t smem_u32(const void* p) {
    uint32_t a;
    asm("{ .reg .u64 t; cvta.to.shared.u64 t, %1; cvt.u32.u64 %0, t; }"
        : "=r"(a) : "l"(p));
    return a;
}
__device__ __forceinline__ void ldsm4(uint32_t* r, uint32_t addr) {
    asm volatile("ldmatrix.sync.aligned.m8n8.x4.shared.b16 {%0,%1,%2,%3}, [%4];"
        : "=r"(r[0]), "=r"(r[1]), "=r"(r[2]), "=r"(r[3]) : "r"(addr));
}
__device__ __forceinline__ void ldsm4t(uint32_t* r, uint32_t addr) {
    asm volatile("ldmatrix.sync.aligned.m8n8.x4.trans.shared.b16 {%0,%1,%2,%3}, [%4];"
        : "=r"(r[0]), "=r"(r[1]), "=r"(r[2]), "=r"(r[3]) : "r"(addr));
}
__device__ __forceinline__ void mma16816(float* d, const uint32_t* a, const uint32_t* b) {
    asm volatile("mma.sync.aligned.m16n8k16.row.col.f32.bf16.bf16.f32 "
        "{%0,%1,%2,%3}, {%4,%5,%6,%7}, {%8,%9}, {%0,%1,%2,%3};"
        : "+f"(d[0]), "+f"(d[1]), "+f"(d[2]), "+f"(d[3])
        : "r"(a[0]), "r"(a[1]), "r"(a[2]), "r"(a[3]), "r"(b[0]), "r"(b[1]));
}
__device__ __forceinline__ uint32_t pack_split(float a, float b, float& ra, float& rb) {
    __nv_bfloat16 ha = __float2bfloat16_rn(a), hb = __float2bfloat16_rn(b);
    ra = a - __bfloat162float(ha);
    rb = b - __bfloat162float(hb);
    return (uint32_t)__bfloat16_as_ushort(ha) | ((uint32_t)__bfloat16_as_ushort(hb) << 16);
}
__device__ __forceinline__ uint32_t pack_bf2(float a, float b) {
    return (uint32_t)__bfloat16_as_ushort(__float2bfloat16_rn(a)) |
           ((uint32_t)__bfloat16_as_ushort(__float2bfloat16_rn(b)) << 16);
}

// ---------------- fp32 -> bf16 hi/lo split (elementwise) ------------------
__global__ __launch_bounds__(256)
void split_kernel(const float* __restrict__ in, __nv_bfloat16* __restrict__ oh,
                  __nv_bfloat16* __restrict__ ol, int n4) {
    int i = blockIdx.x * 256 + threadIdx.x;
    if (i >= n4) return;
    float4 v = reinterpret_cast<const float4*>(in)[i];
    float r0, r1, r2, r3;
    uint32_t h0 = pack_split(v.x, v.y, r0, r1);
    uint32_t h1 = pack_split(v.z, v.w, r2, r3);
    reinterpret_cast<uint2*>(oh)[i] = make_uint2(h0, h1);
    reinterpret_cast<uint2*>(ol)[i] = make_uint2(pack_bf2(r0, r1), pack_bf2(r2, r3));
}

// ====== core: 128x128 CTA tile, 3-pass bf16-split MMA, K = 64*kchunks =====
__device__ __forceinline__ void mma_core_128(
    float acc[2][8][4],
    const __nv_bfloat16* __restrict__ Ah, const __nv_bfloat16* __restrict__ Al, int lda,
    const __nv_bfloat16* __restrict__ Bh, const __nv_bfloat16* __restrict__ Bl, int ldb,
    int kchunks)
{
    char* sAh = dsm;           char* sAl = dsm + 16384;
    char* sBh = dsm + 32768;   char* sBl = dsm + 49152;
    const uint32_t sb = smem_u32(dsm);
    int tid = threadIdx.x, lane = tid & 31, wid = tid >> 5;
    int wm = (wid & 3) << 5, wn = (wid >> 2) << 6;

    uint32_t a_row = wm + (lane & 15);
    uint32_t a_off = a_row * 128, a_sw = (a_row & 7) << 4, a_cb = lane & 16;
    uint32_t b_row = wn + (lane & 7) + ((lane >> 1) & 8);
    uint32_t b_off = b_row * 128, b_sw = (b_row & 7) << 4, b_cb = (lane & 8) << 1;

    for (int kc = 0; kc < kchunks; kc++) {
        if (kc) __syncthreads();
        #pragma unroll
        for (int l = 0; l < 4; l++) {
            int i = tid + l * 256;
            int r = i >> 3, c = i & 7;
            uint32_t doff = r * 128 + ((c * 16) ^ ((r & 7) << 4));
            size_t ga = (size_t)r * lda + kc * 64 + c * 8;
            size_t gb = (size_t)r * ldb + kc * 64 + c * 8;
            *reinterpret_cast<uint4*>(sAh + doff) = *reinterpret_cast<const uint4*>(Ah + ga);
            *reinterpret_cast<uint4*>(sAl + doff) = *reinterpret_cast<const uint4*>(Al + ga);
            *reinterpret_cast<uint4*>(sBh + doff) = *reinterpret_cast<const uint4*>(Bh + gb);
            *reinterpret_cast<uint4*>(sBl + doff) = *reinterpret_cast<const uint4*>(Bl + gb);
        }
        __syncthreads();
        #pragma unroll
        for (int p = 0; p < 3; p++) {
            uint32_t Abase = sb + (p == 2 ? 16384u : 0u);
            uint32_t Bbase = sb + (p == 1 ? 49152u : 32768u);
            #pragma unroll
            for (int k = 0; k < 4; k++) {
                uint32_t a0[4], a1[4];
                uint32_t ca = (uint32_t)(k * 32) + a_cb;
                uint32_t addrA = Abase + a_off + (ca ^ a_sw);
                ldsm4(a0, addrA);
                ldsm4(a1, addrA + 16 * 128);
                uint32_t cb = (uint32_t)(k * 32) + b_cb;
                uint32_t addrB = Bbase + b_off + (cb ^ b_sw);
                uint32_t bfr[4][4];
                #pragma unroll
                for (int j = 0; j < 4; j++) ldsm4(bfr[j], addrB + j * (16 * 128));
                #pragma unroll
                for (int j = 0; j < 4; j++) {
                    mma16816(acc[0][2*j],     a0, &bfr[j][0]);
                    mma16816(acc[0][2*j + 1], a0, &bfr[j][2]);
                    mma16816(acc[1][2*j],     a1, &bfr[j][0]);
                    mma16816(acc[1][2*j + 1], a1, &bfr[j][2]);
                }
            }
        }
    }
}

// ------------- content scores: csc = q @ k^T ------------------------------
__global__ __launch_bounds__(256)
void content_kernel(const __nv_bfloat16* __restrict__ qh, const __nv_bfloat16* __restrict__ ql,
                    const __nv_bfloat16* __restrict__ kh, const __nv_bfloat16* __restrict__ kl,
                    float* __restrict__ csc) {
    int bh = blockIdx.z, m0 = blockIdx.y << 7, n0 = blockIdx.x << 7;
    size_t ab = (size_t)bh * Ss * DH;
    float acc[2][8][4] = {};
    mma_core_128(acc, qh + ab + (size_t)m0 * DH, ql + ab + (size_t)m0 * DH, DH,
                 kh + ab + (size_t)n0 * DH, kl + ab + (size_t)n0 * DH, DH, 1);
    int lane = threadIdx.x & 31, wid = threadIdx.x >> 5;
    int er = ((wid & 3) << 5) + (lane >> 2);
    int ec = ((wid >> 2) << 6) + ((lane & 3) << 1);
    float* out = csc + ((size_t)bh * Ss + m0) * Ss + n0;
    #pragma unroll
    for (int mi = 0; mi < 2; mi++)
        #pragma unroll
        for (int j = 0; j < 8; j++) {
            int r = er + mi * 16, c = ec + j * 8;
            *reinterpret_cast<float2*>(&out[(size_t)r * Ss + c]) =
                make_float2(acc[mi][j][0], acc[mi][j][1]);
            *reinterpret_cast<float2*>(&out[(size_t)(r + 8) * Ss + c]) =
                make_float2(acc[mi][j][2], acc[mi][j][3]);
        }
}

// ------ pos window GEMM: P[bh][sblk][sl][u] = q[s]·rel[u + 896 - s0] ------
__global__ __launch_bounds__(256)
void pos_kernel(const __nv_bfloat16* __restrict__ qh, const __nv_bfloat16* __restrict__ ql,
                const __nv_bfloat16* __restrict__ relh, const __nv_bfloat16* __restrict__ rell,
                float* __restrict__ P) {
    int bh = blockIdx.z, sblk = blockIdx.y, u0 = blockIdx.x << 7;
    int s0 = sblk << 7;
    int rb = 896 - s0 + u0;                       // 0..1920; +127 <= 2047
    size_t ab = (size_t)bh * Ss * DH;
    float acc[2][8][4] = {};
    mma_core_128(acc, qh + ab + (size_t)s0 * DH, ql + ab + (size_t)s0 * DH, DH,
                 relh + (size_t)rb * DH, rell + (size_t)rb * DH, DH, 1);
    int lane = threadIdx.x & 31, wid = threadIdx.x >> 5;
    int er = ((wid & 3) << 5) + (lane >> 2);
    int ec = ((wid >> 2) << 6) + ((lane & 3) << 1);
    float* out = P + (size_t)(bh * 8 + sblk) * 128 * PW + u0;
    #pragma unroll
    for (int mi = 0; mi < 2; mi++)
        #pragma unroll
        for (int j = 0; j < 8; j++) {
            int r = er + mi * 16, c = ec + j * 8;
            *reinterpret_cast<float2*>(&out[(size_t)r * PW + c]) =
                make_float2(acc[mi][j][0], acc[mi][j][1]);
            *reinterpret_cast<float2*>(&out[(size_t)(r + 8) * PW + c]) =
                make_float2(acc[mi][j][2], acc[mi][j][3]);
        }
}

// ------ q/k/v projection: x @ W^T + b -> permuted bf16 hi/lo [bh][s][d] ---
__global__ __launch_bounds__(256)
void proj_qkv_mma(const __nv_bfloat16* __restrict__ xh, const __nv_bfloat16* __restrict__ xl,
                  const __nv_bfloat16* __restrict__ wh, const __nv_bfloat16* __restrict__ wl,
                  const float* __restrict__ bias,
                  __nv_bfloat16* __restrict__ oh, __nv_bfloat16* __restrict__ ol) {
    int n0 = blockIdx.x << 7, m0 = blockIdx.y << 7;
    float acc[2][8][4] = {};
    mma_core_128(acc, xh + (size_t)m0 * Dd, xl + (size_t)m0 * Dd, Dd,
                 wh + (size_t)n0 * Dd, wl + (size_t)n0 * Dd, Dd, 8);
    int lane = threadIdx.x & 31, wid = threadIdx.x >> 5;
    int er = ((wid & 3) << 5) + (lane >> 2);
    int ec = ((wid >> 2) << 6) + ((lane & 3) << 1);
    #pragma unroll
    for (int mi = 0; mi < 2; mi++)
        #pragma unroll
        for (int j = 0; j < 8; j++) {
            int c = n0 + ec + j * 8;
            float b0 = bias[c], b1 = bias[c + 1];
            #pragma unroll
            for (int hf = 0; hf < 2; hf++) {
                int m = m0 + er + mi * 16 + hf * 8;
                float v0 = acc[mi][j][hf*2] + b0, v1 = acc[mi][j][hf*2+1] + b1;
                int b = m >> 10, s = m & 1023;
                int h = c >> 6, d = c & 63;
                size_t off = ((size_t)((((b << 3) | h) << 10) | s)) * DH + d;
                float r0, r1;
                uint32_t hv = pack_split(v0, v1, r0, r1);
                *reinterpret_cast<uint32_t*>(&oh[off]) = hv;
                *reinterpret_cast<uint32_t*>(&ol[off]) = pack_bf2(r0, r1);
            }
        }
}

// ------ output projection: ctx @ Wo^T + bo -> fp32 [4096][512] ------------
__global__ __launch_bounds__(256)
void outproj_mma(const __nv_bfloat16* __restrict__ xh, const __nv_bfloat16* __restrict__ xl,
                 const __nv_bfloat16* __restrict__ wh, const __nv_bfloat16* __restrict__ wl,
                 const float* __restrict__ bias, float* __restrict__ out) {
    int n0 = blockIdx.x << 7, m0 = blockIdx.y << 7;
    float acc[2][8][4] = {};
    mma_core_128(acc, xh + (size_t)m0 * Dd, xl + (size_t)m0 * Dd, Dd,
                 wh + (size_t)n0 * Dd, wl + (size_t)n0 * Dd, Dd, 8);
    int lane = threadIdx.x & 31, wid = threadIdx.x >> 5;
    int er = ((wid & 3) << 5) + (lane >> 2);
    int ec = ((wid >> 2) << 6) + ((lane & 3) << 1);
    #pragma unroll
    for (int mi = 0; mi < 2; mi++)
        #pragma unroll
        for (int j = 0; j < 8; j++) {
            int c = n0 + ec + j * 8;
            float b0 = bias[c], b1 = bias[c + 1];
            int m = m0 + er + mi * 16;
            *reinterpret_cast<float2*>(&out[(size_t)m * Dd + c]) =
                make_float2(acc[mi][j][0] + b0, acc[mi][j][1] + b1);
            *reinterpret_cast<float2*>(&out[(size_t)(m + 8) * Dd + c]) =
                make_float2(acc[mi][j][2] + b0, acc[mi][j][3] + b1);
        }
}

// ---------------- rel projection: rel = pos_emb @ Wp^T + bp ---------------
__global__ __launch_bounds__(256)
void rel_proj_kernel(const float* __restrict__ P, const float* __restrict__ Wp,
                     const float* __restrict__ bp,
                     __nv_bfloat16* __restrict__ oh, __nv_bfloat16* __restrict__ ol) {
    __shared__ float sWT[64 * 64];
    __shared__ float sP[4][64];
    int tid = threadIdx.x;
    for (int i = tid; i < 4096; i += 256) {
        int d = i >> 6, c = i & 63;
        sWT[c * 64 + d] = Wp[i];
    }
    int g = tid >> 6, d = tid & 63;
    int r = blockIdx.x * 4 + g;
    sP[g][d] = (r < RR) ? P[r * 64 + d] : 0.f;
    __syncthreads();
    float acc = bp[d];
    #pragma unroll 16
    for (int c = 0; c < 64; c++) acc += sP[g][c] * sWT[c * 64 + d];
    if (r < RR) {
        __nv_bfloat16 h = __float2bfloat16_rn(acc);
        oh[r * 64 + d] = h;
        ol[r * 64 + d] = __float2bfloat16_rn(acc - __bfloat162float(h));
    }
}

// ------- fused softmax + skew gather: attn + pos_score outputs ------------
__global__ __launch_bounds__(256)
void softmax_fused(const float* __restrict__ csc, const float* __restrict__ P,
                   float* __restrict__ attn, float* __restrict__ psc) {
    const float scl = 0.04419417382415922f;   // 1/sqrt(512)
    int row = blockIdx.x;
    int bh = row >> 10, s = row & 1023;
    int sblk = s >> 7, sl = s & 127;
    size_t base = (size_t)row * Ss;
    const float* crow = csc + base;
    const float* prow = P + ((size_t)(bh * 8 + sblk) * 128 + sl) * PW + (127 - sl);
    int tid = threadIdx.x, t0 = tid * 4;

    float4 cv = *reinterpret_cast<const float4*>(crow + t0);
    float p0 = prow[t0], p1 = prow[t0 + 1], p2 = prow[t0 + 2], p3 = prow[t0 + 3];
    float s0 = (cv.x + p0) * scl, s1 = (cv.y + p1) * scl;
    float s2 = (cv.z + p2) * scl, s3 = (cv.w + p3) * scl;

    float m = fmaxf(fmaxf(s0, s1), fmaxf(s2, s3));
    #pragma unroll
    for (int o = 16; o; o >>= 1) m = fmaxf(m, __shfl_xor_sync(0xffffffffu, m, o));
    __shared__ float red[8];
    int wid = tid >> 5, lid = tid & 31;
    if (lid == 0) red[wid] = m;
    __syncthreads();
    m = red[0];
    #pragma unroll
    for (int w = 1; w < 8; w++) m = fmaxf(m, red[w]);

    float e0 = __expf(s0 - m), e1 = __expf(s1 - m);
    float e2 = __expf(s2 - m), e3 = __expf(s3 - m);
    float sum = (e0 + e1) + (e2 + e3);
    #pragma unroll
    for (int o = 16; o; o >>= 1) sum += __shfl_xor_sync(0xffffffffu, sum, o);
    __syncthreads();
    if (lid == 0) red[wid] = sum;
    __syncthreads();
    float tot = red[0];
    #pragma unroll
    for (int w = 1; w < 8; w++) tot += red[w];
    float inv = 1.0f / tot;

    *reinterpret_cast<float4*>(&attn[base + t0]) =
        make_float4(e0 * inv, e1 * inv, e2 * inv, e3 * inv);
    *reinterpret_cast<float4*>(&psc[base + t0]) = make_float4(p0, p1, p2, p3);
}

// ------ ctx = attn @ v (split on the fly) -> bf16 hi/lo [b][s][h*64+d] ----
__global__ __launch_bounds__(256)
void ctx_mma(const float* __restrict__ attn,
             const __nv_bfloat16* __restrict__ vh, const __nv_bfloat16* __restrict__ vl,
             __nv_bfloat16* __restrict__ ch, __nv_bfloat16* __restrict__ cl) {
    char* sAh = dsm;           char* sAl = dsm + 16384;
    char* sVh = dsm + 32768;   char* sVl = dsm + 40960;
    const uint32_t sb = smem_u32(dsm);
    int bh = blockIdx.y, s0 = blockIdx.x << 7;
    const float* ab = attn + ((size_t)bh * Ss + s0) * Ss;
    const __nv_bfloat16* vhb = vh + (size_t)bh * Ss * DH;
    const __nv_bfloat16* vlb = vl + (size_t)bh * Ss * DH;
    int tid = threadIdx.x, lane = tid & 31, wid = tid >> 5;
    int wm = (wid & 3) << 5, wn = (wid >> 2) << 5;

    uint32_t a_row = wm + (lane & 15);
    uint32_t a_off = a_row * 128, a_sw = (a_row & 7) << 4, a_cb = lane & 16;
    uint32_t bt = (lane & 7) + (lane & 8);       // t within k16 step
    uint32_t b_cb16 = lane & 16;

    float acc[2][4][4] = {};
    for (int kc = 0; kc < 16; kc++) {
        if (kc) __syncthreads();
        #pragma unroll
        for (int l = 0; l < 8; l++) {            // 2048 float4 of attn
            int i = tid + l * 256;
            int r = i >> 4, c = i & 15;
            float4 v = *reinterpret_cast<const float4*>(ab + (size_t)r * Ss + kc * 64 + c * 4);
            float r0, r1, r2, r3;
            uint32_t h0 = pack_split(v.x, v.y, r0, r1);
            uint32_t h1 = pack_split(v.z, v.w, r2, r3);
            uint32_t doff = r * 128 + ((c * 8) ^ ((r & 7) << 4));
            *reinterpret_cast<uint2*>(sAh + doff) = make_uint2(h0, h1);
            *reinterpret_cast<uint2*>(sAl + doff) = make_uint2(pack_bf2(r0, r1), pack_bf2(r2, r3));
        }
        #pragma unroll
        for (int l = 0; l < 2; l++) {            // 512 uint4 of v tiles
            int i = tid + l * 256;
            int r = i >> 3, c = i & 7;
            uint32_t doff = r * 128 + ((c * 16) ^ ((r & 7) << 4));
            size_t g = (size_t)(kc * 64 + r) * DH + c * 8;
            *reinterpret_cast<uint4*>(sVh + doff) = *reinterpret_cast<const uint4*>(vhb + g);
            *reinterpret_cast<uint4*>(sVl + doff) = *reinterpret_cast<const uint4*>(vlb + g);
        }
        __syncthreads();
        #pragma unroll
        for (int p = 0; p < 3; p++) {
            uint32_t Abase = sb + (p == 2 ? 16384u : 0u);
            uint32_t Vbase = sb + (p == 1 ? 40960u : 32768u);
            #pragma unroll
            for (int k = 0; k < 4; k++) {
                uint32_t a0[4], a1[4];
                uint32_t ca = (uint32_t)(k * 32) + a_cb;
                uint32_t addrA = Abase + a_off + (ca ^ a_sw);
                ldsm4(a0, addrA);
                ldsm4(a1, addrA + 16 * 128);
                uint32_t bfr[2][4];
                #pragma unroll
                for (int l2 = 0; l2 < 2; l2++) {
                    uint32_t t = (uint32_t)(k * 16) + bt;
                    uint32_t cb = (uint32_t)((wn + l2 * 16) * 2) + b_cb16;
                    uint32_t addrB = Vbase + t * 128 + (cb ^ ((t & 7) << 4));
                    ldsm4t(bfr[l2], addrB);
                }
                #pragma unroll
                for (int j = 0; j < 4; j++) {
                    const uint32_t* bb = (j & 1) ? &bfr[j >> 1][2] : &bfr[j >> 1][0];
                    mma16816(acc[0][j], a0, bb);
                    mma16816(acc[1][j], a1, bb);
                }
            }
        }
    }
    int b = bh >> 3, h = bh & 7;
    int er = wm + (lane >> 2), ec = wn + ((lane & 3) << 1);
    #pragma unroll
    for (int mi = 0; mi < 2; mi++)
        #pragma unroll
        for (int j = 0; j < 4; j++)
            #pragma unroll
            for (int hf = 0; hf < 2; hf++) {
                int s = s0 + er + mi * 16 + hf * 8;
                int d = ec + j * 8;
                float v0 = acc[mi][j][hf*2], v1 = acc[mi][j][hf*2+1];
                size_t off = ((size_t)((b << 10) | s)) * Dd + (h << 6) + d;
                float r0, r1;
                uint32_t hv = pack_split(v0, v1, r0, r1);
                *reinterpret_cast<uint32_t*>(&ch[off]) = hv;
                *reinterpret_cast<uint32_t*>(&cl[off]) = pack_bf2(r0, r1);
            }
}

// -------------------------------------------------------------------------
extern "C" void kernel_launch(void* const* d_in, const int* in_sizes, int n_in,
                              void* d_out, int out_size) {
    const float* query   = (const float*)d_in[0];
    const float* key     = (const float*)d_in[1];
    const float* value   = (const float*)d_in[2];
    const float* pos_emb = (const float*)d_in[3];
    const float* Wq = (const float*)d_in[4];
    const float* bq = (const float*)d_in[5];
    const float* Wk = (const float*)d_in[6];
    const float* bk = (const float*)d_in[7];
    const float* Wv = (const float*)d_in[8];
    const float* bv = (const float*)d_in[9];
    const float* Wo = (const float*)d_in[10];
    const float* bo = (const float*)d_in[11];
    const float* Wp = (const float*)d_in[12];
    const float* bp = (const float*)d_in[13];

    float* out  = (float*)d_out;
    float* attn = out  + (size_t)Bb * Ss * Dd;
    float* csc  = attn + (size_t)Bb * Hh * Ss * Ss;
    float* psc  = csc  + (size_t)Bb * Hh * Ss * Ss;

    __nv_bfloat16 *inqh, *inql, *inkh, *inkl, *invh, *invl;
    __nv_bfloat16 *wqh, *wql, *wkh, *wkl, *wvh, *wvl, *woh, *wol;
    __nv_bfloat16 *qh, *ql, *kh, *kl, *vh, *vl, *relh, *rell, *ctxh, *ctxl;
    float *Pp;
    cudaGetSymbolAddress((void**)&inqh, g_inqh); cudaGetSymbolAddress((void**)&inql, g_inql);
    cudaGetSymbolAddress((void**)&inkh, g_inkh); cudaGetSymbolAddress((void**)&inkl, g_inkl);
    cudaGetSymbolAddress((void**)&invh, g_invh); cudaGetSymbolAddress((void**)&invl, g_invl);
    cudaGetSymbolAddress((void**)&wqh, g_wqh);   cudaGetSymbolAddress((void**)&wql, g_wql);
    cudaGetSymbolAddress((void**)&wkh, g_wkh);   cudaGetSymbolAddress((void**)&wkl, g_wkl);
    cudaGetSymbolAddress((void**)&wvh, g_wvh);   cudaGetSymbolAddress((void**)&wvl, g_wvl);
    cudaGetSymbolAddress((void**)&woh, g_woh);   cudaGetSymbolAddress((void**)&wol, g_wol);
    cudaGetSymbolAddress((void**)&qh, g_qh);     cudaGetSymbolAddress((void**)&ql, g_ql);
    cudaGetSymbolAddress((void**)&kh, g_kh);     cudaGetSymbolAddress((void**)&kl, g_kl);
    cudaGetSymbolAddress((void**)&vh, g_vh);     cudaGetSymbolAddress((void**)&vl, g_vl);
    cudaGetSymbolAddress((void**)&relh, g_relh); cudaGetSymbolAddress((void**)&rell, g_rell);
    cudaGetSymbolAddress((void**)&ctxh, g_ctxh); cudaGetSymbolAddress((void**)&ctxl, g_ctxl);
    cudaGetSymbolAddress((void**)&Pp, g_P);

    cudaFuncSetAttribute(proj_qkv_mma,  cudaFuncAttributeMaxDynamicSharedMemorySize, 65536);
    cudaFuncSetAttribute(outproj_mma,   cudaFuncAttributeMaxDynamicSharedMemorySize, 65536);
    cudaFuncSetAttribute(content_kernel,cudaFuncAttributeMaxDynamicSharedMemorySize, 65536);
    cudaFuncSetAttribute(pos_kernel,    cudaFuncAttributeMaxDynamicSharedMemorySize, 65536);
    cudaFuncSetAttribute(ctx_mma,       cudaFuncAttributeMaxDynamicSharedMemorySize, 49152);

    split_kernel<<<2048, 256>>>(query, inqh, inql, 524288);
    split_kernel<<<2048, 256>>>(key,   inkh, inkl, 524288);
    split_kernel<<<2048, 256>>>(value, invh, invl, 524288);
    split_kernel<<<256, 256>>>(Wq, wqh, wql, 65536);
    split_kernel<<<256, 256>>>(Wk, wkh, wkl, 65536);
    split_kernel<<<256, 256>>>(Wv, wvh, wvl, 65536);
    split_kernel<<<256, 256>>>(Wo, woh, wol, 65536);
    rel_proj_kernel<<<512, 256>>>(pos_emb, Wp, bp, relh, rell);

    proj_qkv_mma<<<dim3(4, 32), 256, 65536>>>(inqh, inql, wqh, wql, bq, qh, ql);
    proj_qkv_mma<<<dim3(4, 32), 256, 65536>>>(inkh, inkl, wkh, wkl, bk, kh, kl);
    proj_qkv_mma<<<dim3(4, 32), 256, 65536>>>(invh, invl, wvh, wvl, bv, vh, vl);

    content_kernel<<<dim3(8, 8, 32), 256, 65536>>>(qh, ql, kh, kl, csc);
    pos_kernel<<<dim3(9, 8, 32), 256, 65536>>>(qh, ql, relh, rell, Pp);

    softmax_fused<<<Bb * Hh * Ss, 256>>>(csc, Pp, attn, psc);
    ctx_mma<<<dim3(8, 32), 256, 49152>>>(attn, vh, vl, ctxh, ctxl);
    outproj_mma<<<dim3(4, 32), 256, 65536>>>(ctxh, ctxl, woh, wol, bo, out);
}

// round 6
// speedup vs baseline: 2.7533x; 1.0085x over previous
#include <cuda_runtime.h>
#include <cuda_bf16.h>
#include <cstdint>

#define Bb 4
#define Ss 1024
#define Dd 512
#define Hh 8
#define DH 64
#define RR 2047
#define RPAD 2304

// ---------------- scratch (device globals; zero-init, no allocation) ------
__device__ __nv_bfloat16 g_inqh[4096*512], g_inql[4096*512];
__device__ __nv_bfloat16 g_inkh[4096*512], g_inkl[4096*512];
__device__ __nv_bfloat16 g_invh[4096*512], g_invl[4096*512];
__device__ __nv_bfloat16 g_wqh[512*512], g_wql[512*512];
__device__ __nv_bfloat16 g_wkh[512*512], g_wkl[512*512];
__device__ __nv_bfloat16 g_wvh[512*512], g_wvl[512*512];
__device__ __nv_bfloat16 g_woh[512*512], g_wol[512*512];
__device__ __nv_bfloat16 g_qh[32*1024*64], g_ql[32*1024*64];
__device__ __nv_bfloat16 g_kh[32*1024*64], g_kl[32*1024*64];
__device__ __nv_bfloat16 g_vh[32*1024*64], g_vl[32*1024*64];
__device__ __nv_bfloat16 g_relh[RPAD*64], g_rell[RPAD*64];   // rows >=2047 stay 0
__device__ __nv_bfloat16 g_ctxh[4096*512], g_ctxl[4096*512];

extern __shared__ char dsm[];

// ======================= helpers =========================================
__device__ __forceinline__ uint32_t smem_u32(const void* p) {
    uint32_t a;
    asm("{ .reg .u64 t; cvta.to.shared.u64 t, %1; cvt.u32.u64 %0, t; }"
        : "=r"(a) : "l"(p));
    return a;
}
__device__ __forceinline__ void ldsm4(uint32_t* r, uint32_t addr) {
    asm volatile("ldmatrix.sync.aligned.m8n8.x4.shared.b16 {%0,%1,%2,%3}, [%4];"
        : "=r"(r[0]), "=r"(r[1]), "=r"(r[2]), "=r"(r[3]) : "r"(addr));
}
__device__ __forceinline__ void ldsm4t(uint32_t* r, uint32_t addr) {
    asm volatile("ldmatrix.sync.aligned.m8n8.x4.trans.shared.b16 {%0,%1,%2,%3}, [%4];"
        : "=r"(r[0]), "=r"(r[1]), "=r"(r[2]), "=r"(r[3]) : "r"(addr));
}
__device__ __forceinline__ void mma16816(float* d, const uint32_t* a, const uint32_t* b) {
    asm volatile("mma.sync.aligned.m16n8k16.row.col.f32.bf16.bf16.f32 "
        "{%0,%1,%2,%3}, {%4,%5,%6,%7}, {%8,%9}, {%0,%1,%2,%3};"
        : "+f"(d[0]), "+f"(d[1]), "+f"(d[2]), "+f"(d[3])
        : "r"(a[0]), "r"(a[1]), "r"(a[2]), "r"(a[3]), "r"(b[0]), "r"(b[1]));
}
__device__ __forceinline__ void cp16(uint32_t dst, const void* src) {
    asm volatile("cp.async.cg.shared.global [%0], [%1], 16;" :: "r"(dst), "l"(src));
}
#define CP_COMMIT() asm volatile("cp.async.commit_group;" ::: "memory")
#define CP_WAIT(N)  asm volatile("cp.async.wait_group %0;" :: "n"(N) : "memory")

__device__ __forceinline__ uint32_t pack_split(float a, float b, float& ra, float& rb) {
    __nv_bfloat16 ha = __float2bfloat16_rn(a), hb = __float2bfloat16_rn(b);
    ra = a - __bfloat162float(ha);
    rb = b - __bfloat162float(hb);
    return (uint32_t)__bfloat16_as_ushort(ha) | ((uint32_t)__bfloat16_as_ushort(hb) << 16);
}
__device__ __forceinline__ uint32_t pack_bf2(float a, float b) {
    return (uint32_t)__bfloat16_as_ushort(__float2bfloat16_rn(a)) |
           ((uint32_t)__bfloat16_as_ushort(__float2bfloat16_rn(b)) << 16);
}

// ---------------- fp32 -> bf16 hi/lo split (elementwise) ------------------
__global__ __launch_bounds__(256)
void split_kernel(const float* __restrict__ in, __nv_bfloat16* __restrict__ oh,
                  __nv_bfloat16* __restrict__ ol, int n4) {
    int i = blockIdx.x * 256 + threadIdx.x;
    if (i >= n4) return;
    float4 v = reinterpret_cast<const float4*>(in)[i];
    float r0, r1, r2, r3;
    uint32_t h0 = pack_split(v.x, v.y, r0, r1);
    uint32_t h1 = pack_split(v.z, v.w, r2, r3);
    reinterpret_cast<uint2*>(oh)[i] = make_uint2(h0, h1);
    reinterpret_cast<uint2*>(ol)[i] = make_uint2(pack_bf2(r0, r1), pack_bf2(r2, r3));
}

// ====== core: 128x128 CTA tile, 3-pass bf16-split MMA, K = 64*kchunks =====
// STAGES=1: single 64KB buffer (high-grid kernels); STAGES=2: 128KB pipeline.
template<int STAGES>
__device__ __forceinline__ void mma_core_128(
    float acc[2][8][4],
    const __nv_bfloat16* __restrict__ Ah, const __nv_bfloat16* __restrict__ Al, int lda,
    const __nv_bfloat16* __restrict__ Bh, const __nv_bfloat16* __restrict__ Bl, int ldb,
    int kchunks)
{
    const uint32_t sb = smem_u32(dsm);
    int tid = threadIdx.x, lane = tid & 31, wid = tid >> 5;
    int wm = (wid & 3) << 5, wn = (wid >> 2) << 6;

    uint32_t a_row = wm + (lane & 15);
    uint32_t a_off = a_row * 128, a_sw = (a_row & 7) << 4, a_cb = lane & 16;
    uint32_t b_row = wn + (lane & 7) + ((lane >> 1) & 8);
    uint32_t b_off = b_row * 128, b_sw = (b_row & 7) << 4, b_cb = (lane & 8) << 1;

    // precompute this thread's 4 fill slots
    int fr[4], fc[4];
    #pragma unroll
    for (int l = 0; l < 4; l++) {
        int i = tid + l * 256;
        fr[l] = i >> 3; fc[l] = i & 7;
    }

    auto issue = [&](int kc, int stage) {
        uint32_t s0 = sb + stage * 65536u;
        #pragma unroll
        for (int l = 0; l < 4; l++) {
            int r = fr[l], c = fc[l];
            uint32_t doff = r * 128 + ((c * 16) ^ ((r & 7) << 4));
            size_t ga = (size_t)r * lda + kc * 64 + c * 8;
            size_t gb = (size_t)r * ldb + kc * 64 + c * 8;
            cp16(s0 + doff,          Ah + ga);
            cp16(s0 + 16384 + doff,  Al + ga);
            cp16(s0 + 32768 + doff,  Bh + gb);
            cp16(s0 + 49152 + doff,  Bl + gb);
        }
        CP_COMMIT();
    };

    issue(0, 0);
    for (int kc = 0; kc < kchunks; kc++) {
        int st = (STAGES == 2) ? (kc & 1) : 0;
        if (STAGES == 2 && kc + 1 < kchunks) {
            issue(kc + 1, (kc + 1) & 1);
            CP_WAIT(1);
        } else {
            CP_WAIT(0);
        }
        __syncthreads();
        uint32_t base = sb + st * 65536u;
        #pragma unroll
        for (int p = 0; p < 3; p++) {
            uint32_t Abase = base + (p == 2 ? 16384u : 0u);
            uint32_t Bbase = base + 32768u + (p == 1 ? 16384u : 0u);
            #pragma unroll
            for (int k = 0; k < 4; k++) {
                uint32_t a0[4], a1[4];
                uint32_t ca = (uint32_t)(k * 32) + a_cb;
                uint32_t addrA = Abase + a_off + (ca ^ a_sw);
                ldsm4(a0, addrA);
                ldsm4(a1, addrA + 16 * 128);
                uint32_t cb = (uint32_t)(k * 32) + b_cb;
                uint32_t addrB = Bbase + b_off + (cb ^ b_sw);
                uint32_t bfr[4][4];
                #pragma unroll
                for (int j = 0; j < 4; j++) ldsm4(bfr[j], addrB + j * (16 * 128));
                #pragma unroll
                for (int j = 0; j < 4; j++) {
                    mma16816(acc[0][2*j],     a0, &bfr[j][0]);
                    mma16816(acc[0][2*j + 1], a0, &bfr[j][2]);
                    mma16816(acc[1][2*j],     a1, &bfr[j][0]);
                    mma16816(acc[1][2*j + 1], a1, &bfr[j][2]);
                }
            }
        }
        if (kc + 1 < kchunks) __syncthreads();
    }
}

// ------------- content scores: csc = q @ k^T ------------------------------
__global__ __launch_bounds__(256)
void content_kernel(const __nv_bfloat16* __restrict__ qh, const __nv_bfloat16* __restrict__ ql,
                    const __nv_bfloat16* __restrict__ kh, const __nv_bfloat16* __restrict__ kl,
                    float* __restrict__ csc) {
    int bh = blockIdx.z, m0 = blockIdx.y << 7, n0 = blockIdx.x << 7;
    size_t ab = (size_t)bh * Ss * DH;
    float acc[2][8][4] = {};
    mma_core_128<1>(acc, qh + ab + (size_t)m0 * DH, ql + ab + (size_t)m0 * DH, DH,
                    kh + ab + (size_t)n0 * DH, kl + ab + (size_t)n0 * DH, DH, 1);
    int lane = threadIdx.x & 31, wid = threadIdx.x >> 5;
    int er = ((wid & 3) << 5) + (lane >> 2);
    int ec = ((wid >> 2) << 6) + ((lane & 3) << 1);
    float* out = csc + ((size_t)bh * Ss + m0) * Ss + n0;
    #pragma unroll
    for (int mi = 0; mi < 2; mi++)
        #pragma unroll
        for (int j = 0; j < 8; j++) {
            int r = er + mi * 16, c = ec + j * 8;
            *reinterpret_cast<float2*>(&out[(size_t)r * Ss + c]) =
                make_float2(acc[mi][j][0], acc[mi][j][1]);
            *reinterpret_cast<float2*>(&out[(size_t)(r + 8) * Ss + c]) =
                make_float2(acc[mi][j][2], acc[mi][j][3]);
        }
}

// ------ pos scores with fused skew: psc[s][t] = q[s]·rel[t-s+1023] --------
// GEMM over window u; epilogue scatters u -> t = u + sl - 127 (predicated).
__global__ __launch_bounds__(256)
void pos_kernel(const __nv_bfloat16* __restrict__ qh, const __nv_bfloat16* __restrict__ ql,
                const __nv_bfloat16* __restrict__ relh, const __nv_bfloat16* __restrict__ rell,
                float* __restrict__ psc) {
    int bh = blockIdx.z, sblk = blockIdx.y, u0 = blockIdx.x << 7;
    int s0 = sblk << 7;
    int rb = 896 - s0 + u0;                       // rel row for u-local 0
    size_t ab = (size_t)bh * Ss * DH;
    float acc[2][8][4] = {};
    mma_core_128<1>(acc, qh + ab + (size_t)s0 * DH, ql + ab + (size_t)s0 * DH, DH,
                    relh + (size_t)rb * DH, rell + (size_t)rb * DH, DH, 1);
    int lane = threadIdx.x & 31, wid = threadIdx.x >> 5;
    int er = ((wid & 3) << 5) + (lane >> 2);
    int ec = ((wid >> 2) << 6) + ((lane & 3) << 1);
    float* pbase = psc + ((size_t)bh * Ss + s0) * Ss;
    #pragma unroll
    for (int mi = 0; mi < 2; mi++)
        #pragma unroll
        for (int j = 0; j < 8; j++) {
            int u = u0 + ec + j * 8;
            #pragma unroll
            for (int hf = 0; hf < 2; hf++) {
                int sl = er + mi * 16 + hf * 8;
                int t = u + sl - 127;
                float v0 = acc[mi][j][hf*2], v1 = acc[mi][j][hf*2+1];
                if ((unsigned)t < 1024u)       pbase[(size_t)sl * Ss + t] = v0;
                if ((unsigned)(t + 1) < 1024u) pbase[(size_t)sl * Ss + t + 1] = v1;
            }
        }
}

// ------ q/k/v projection: x @ W^T + b -> permuted bf16 hi/lo [bh][s][d] ---
__global__ __launch_bounds__(256)
void proj_qkv_mma(const __nv_bfloat16* __restrict__ xh, const __nv_bfloat16* __restrict__ xl,
                  const __nv_bfloat16* __restrict__ wh, const __nv_bfloat16* __restrict__ wl,
                  const float* __restrict__ bias,
                  __nv_bfloat16* __restrict__ oh, __nv_bfloat16* __restrict__ ol) {
    int n0 = blockIdx.x << 7, m0 = blockIdx.y << 7;
    float acc[2][8][4] = {};
    mma_core_128<2>(acc, xh + (size_t)m0 * Dd, xl + (size_t)m0 * Dd, Dd,
                    wh + (size_t)n0 * Dd, wl + (size_t)n0 * Dd, Dd, 8);
    int lane = threadIdx.x & 31, wid = threadIdx.x >> 5;
    int er = ((wid & 3) << 5) + (lane >> 2);
    int ec = ((wid >> 2) << 6) + ((lane & 3) << 1);
    #pragma unroll
    for (int mi = 0; mi < 2; mi++)
        #pragma unroll
        for (int j = 0; j < 8; j++) {
            int c = n0 + ec + j * 8;
            float b0 = bias[c], b1 = bias[c + 1];
            #pragma unroll
            for (int hf = 0; hf < 2; hf++) {
                int m = m0 + er + mi * 16 + hf * 8;
                float v0 = acc[mi][j][hf*2] + b0, v1 = acc[mi][j][hf*2+1] + b1;
                int b = m >> 10, s = m & 1023;
                int h = c >> 6, d = c & 63;
                size_t off = ((size_t)((((b << 3) | h) << 10) | s)) * DH + d;
                float r0, r1;
                uint32_t hv = pack_split(v0, v1, r0, r1);
                *reinterpret_cast<uint32_t*>(&oh[off]) = hv;
                *reinterpret_cast<uint32_t*>(&ol[off]) = pack_bf2(r0, r1);
            }
        }
}

// ------ output projection: ctx @ Wo^T + bo -> fp32 [4096][512] ------------
__global__ __launch_bounds__(256)
void outproj_mma(const __nv_bfloat16* __restrict__ xh, const __nv_bfloat16* __restrict__ xl,
                 const __nv_bfloat16* __restrict__ wh, const __nv_bfloat16* __restrict__ wl,
                 const float* __restrict__ bias, float* __restrict__ out) {
    int n0 = blockIdx.x << 7, m0 = blockIdx.y << 7;
    float acc[2][8][4] = {};
    mma_core_128<2>(acc, xh + (size_t)m0 * Dd, xl + (size_t)m0 * Dd, Dd,
                    wh + (size_t)n0 * Dd, wl + (size_t)n0 * Dd, Dd, 8);
    int lane = threadIdx.x & 31, wid = threadIdx.x >> 5;
    int er = ((wid & 3) << 5) + (lane >> 2);
    int ec = ((wid >> 2) << 6) + ((lane & 3) << 1);
    #pragma unroll
    for (int mi = 0; mi < 2; mi++)
        #pragma unroll
        for (int j = 0; j < 8; j++) {
            int c = n0 + ec + j * 8;
            float b0 = bias[c], b1 = bias[c + 1];
            int m = m0 + er + mi * 16;
            *reinterpret_cast<float2*>(&out[(size_t)m * Dd + c]) =
                make_float2(acc[mi][j][0] + b0, acc[mi][j][1] + b1);
            *reinterpret_cast<float2*>(&out[(size_t)(m + 8) * Dd + c]) =
                make_float2(acc[mi][j][2] + b0, acc[mi][j][3] + b1);
        }
}

// ---------------- rel projection: rel = pos_emb @ Wp^T + bp ---------------
__global__ __launch_bounds__(256)
void rel_proj_kernel(const float* __restrict__ P, const float* __restrict__ Wp,
                     const float* __restrict__ bp,
                     __nv_bfloat16* __restrict__ oh, __nv_bfloat16* __restrict__ ol) {
    __shared__ float sWT[64 * 64];
    __shared__ float sP[4][64];
    int tid = threadIdx.x;
    for (int i = tid; i < 4096; i += 256) {
        int d = i >> 6, c = i & 63;
        sWT[c * 64 + d] = Wp[i];
    }
    int g = tid >> 6, d = tid & 63;
    int r = blockIdx.x * 4 + g;
    sP[g][d] = (r < RR) ? P[r * 64 + d] : 0.f;
    __syncthreads();
    float acc = bp[d];
    #pragma unroll 16
    for (int c = 0; c < 64; c++) acc += sP[g][c] * sWT[c * 64 + d];
    if (r < RR) {
        __nv_bfloat16 h = __float2bfloat16_rn(acc);
        oh[r * 64 + d] = h;
        ol[r * 64 + d] = __float2bfloat16_rn(acc - __bfloat162float(h));
    }
}

// ------- softmax over (csc+psc)/sqrt(512): writes attn --------------------
__global__ __launch_bounds__(256)
void softmax_fused(const float* __restrict__ csc, const float* __restrict__ psc,
                   float* __restrict__ attn) {
    const float scl = 0.04419417382415922f;   // 1/sqrt(512)
    size_t base = (size_t)blockIdx.x * Ss;
    int tid = threadIdx.x, t0 = tid * 4;

    float4 cv = *reinterpret_cast<const float4*>(csc + base + t0);
    float4 pv = *reinterpret_cast<const float4*>(psc + base + t0);
    float s0 = (cv.x + pv.x) * scl, s1 = (cv.y + pv.y) * scl;
    float s2 = (cv.z + pv.z) * scl, s3 = (cv.w + pv.w) * scl;

    float m = fmaxf(fmaxf(s0, s1), fmaxf(s2, s3));
    #pragma unroll
    for (int o = 16; o; o >>= 1) m = fmaxf(m, __shfl_xor_sync(0xffffffffu, m, o));
    __shared__ float red[8];
    int wid = tid >> 5, lid = tid & 31;
    if (lid == 0) red[wid] = m;
    __syncthreads();
    m = red[0];
    #pragma unroll
    for (int w = 1; w < 8; w++) m = fmaxf(m, red[w]);

    float e0 = __expf(s0 - m), e1 = __expf(s1 - m);
    float e2 = __expf(s2 - m), e3 = __expf(s3 - m);
    float sum = (e0 + e1) + (e2 + e3);
    #pragma unroll
    for (int o = 16; o; o >>= 1) sum += __shfl_xor_sync(0xffffffffu, sum, o);
    __syncthreads();
    if (lid == 0) red[wid] = sum;
    __syncthreads();
    float tot = red[0];
    #pragma unroll
    for (int w = 1; w < 8; w++) tot += red[w];
    float inv = 1.0f / tot;

    *reinterpret_cast<float4*>(&attn[base + t0]) =
        make_float4(e0 * inv, e1 * inv, e2 * inv, e3 * inv);
}

// ------ ctx = attn @ v (split on the fly) -> bf16 hi/lo [b][s][h*64+d] ----
__global__ __launch_bounds__(256)
void ctx_mma(const float* __restrict__ attn,
             const __nv_bfloat16* __restrict__ vh, const __nv_bfloat16* __restrict__ vl,
             __nv_bfloat16* __restrict__ ch, __nv_bfloat16* __restrict__ cl) {
    char* sAh = dsm;           char* sAl = dsm + 16384;
    char* sVh = dsm + 32768;   char* sVl = dsm + 40960;
    const uint32_t sb = smem_u32(dsm);
    int bh = blockIdx.y, s0 = blockIdx.x << 7;
    const float* ab = attn + ((size_t)bh * Ss + s0) * Ss;
    const __nv_bfloat16* vhb = vh + (size_t)bh * Ss * DH;
    const __nv_bfloat16* vlb = vl + (size_t)bh * Ss * DH;
    int tid = threadIdx.x, lane = tid & 31, wid = tid >> 5;
    int wm = (wid & 3) << 5, wn = (wid >> 2) << 5;

    uint32_t a_row = wm + (lane & 15);
    uint32_t a_off = a_row * 128, a_sw = (a_row & 7) << 4, a_cb = lane & 16;
    uint32_t bt = (lane & 7) + (lane & 8);       // t within k16 step
    uint32_t b_cb16 = lane & 16;

    float acc[2][4][4] = {};
    for (int kc = 0; kc < 16; kc++) {
        if (kc) __syncthreads();
        // V tiles via cp.async, overlapped under the attn convert/fill below
        #pragma unroll
        for (int l = 0; l < 2; l++) {
            int i = tid + l * 256;
            int r = i >> 3, c = i & 7;
            uint32_t doff = r * 128 + ((c * 16) ^ ((r & 7) << 4));
            size_t g = (size_t)(kc * 64 + r) * DH + c * 8;
            cp16(sb + 32768 + doff, vhb + g);
            cp16(sb + 40960 + doff, vlb + g);
        }
        CP_COMMIT();
        #pragma unroll
        for (int l = 0; l < 8; l++) {            // 2048 float4 of attn
            int i = tid + l * 256;
            int r = i >> 4, c = i & 15;
            float4 v = *reinterpret_cast<const float4*>(ab + (size_t)r * Ss + kc * 64 + c * 4);
            float r0, r1, r2, r3;
            uint32_t h0 = pack_split(v.x, v.y, r0, r1);
            uint32_t h1 = pack_split(v.z, v.w, r2, r3);
            uint32_t doff = r * 128 + ((c * 8) ^ ((r & 7) << 4));
            *reinterpret_cast<uint2*>(sAh + doff) = make_uint2(h0, h1);
            *reinterpret_cast<uint2*>(sAl + doff) = make_uint2(pack_bf2(r0, r1), pack_bf2(r2, r3));
        }
        CP_WAIT(0);
        __syncthreads();
        #pragma unroll
        for (int p = 0; p < 3; p++) {
            uint32_t Abase = sb + (p == 2 ? 16384u : 0u);
            uint32_t Vbase = sb + (p == 1 ? 40960u : 32768u);
            #pragma unroll
            for (int k = 0; k < 4; k++) {
                uint32_t a0[4], a1[4];
                uint32_t ca = (uint32_t)(k * 32) + a_cb;
                uint32_t addrA = Abase + a_off + (ca ^ a_sw);
                ldsm4(a0, addrA);
                ldsm4(a1, addrA + 16 * 128);
                uint32_t bfr[2][4];
                #pragma unroll
                for (int l2 = 0; l2 < 2; l2++) {
                    uint32_t t = (uint32_t)(k * 16) + bt;
                    uint32_t cb = (uint32_t)((wn + l2 * 16) * 2) + b_cb16;
                    uint32_t addrB = Vbase + t * 128 + (cb ^ ((t & 7) << 4));
                    ldsm4t(bfr[l2], addrB);
                }
                #pragma unroll
                for (int j = 0; j < 4; j++) {
                    const uint32_t* bb = (j & 1) ? &bfr[j >> 1][2] : &bfr[j >> 1][0];
                    mma16816(acc[0][j], a0, bb);
                    mma16816(acc[1][j], a1, bb);
                }
            }
        }
    }
    int b = bh >> 3, h = bh & 7;
    int er = wm + (lane >> 2), ec = wn + ((lane & 3) << 1);
    #pragma unroll
    for (int mi = 0; mi < 2; mi++)
        #pragma unroll
        for (int j = 0; j < 4; j++)
            #pragma unroll
            for (int hf = 0; hf < 2; hf++) {
                int s = s0 + er + mi * 16 + hf * 8;
                int d = ec + j * 8;
                float v0 = acc[mi][j][hf*2], v1 = acc[mi][j][hf*2+1];
                size_t off = ((size_t)((b << 10) | s)) * Dd + (h << 6) + d;
                float r0, r1;
                uint32_t hv = pack_split(v0, v1, r0, r1);
                *reinterpret_cast<uint32_t*>(&ch[off]) = hv;
                *reinterpret_cast<uint32_t*>(&cl[off]) = pack_bf2(r0, r1);
            }
}

// -------------------------------------------------------------------------
extern "C" void kernel_launch(void* const* d_in, const int* in_sizes, int n_in,
                              void* d_out, int out_size) {
    const float* query   = (const float*)d_in[0];
    const float* key     = (const float*)d_in[1];
    const float* value   = (const float*)d_in[2];
    const float* pos_emb = (const float*)d_in[3];
    const float* Wq = (const float*)d_in[4];
    const float* bq = (const float*)d_in[5];
    const float* Wk = (const float*)d_in[6];
    const float* bk = (const float*)d_in[7];
    const float* Wv = (const float*)d_in[8];
    const float* bv = (const float*)d_in[9];
    const float* Wo = (const float*)d_in[10];
    const float* bo = (const float*)d_in[11];
    const float* Wp = (const float*)d_in[12];
    const float* bp = (const float*)d_in[13];

    float* out  = (float*)d_out;
    float* attn = out  + (size_t)Bb * Ss * Dd;
    float* csc  = attn + (size_t)Bb * Hh * Ss * Ss;
    float* psc  = csc  + (size_t)Bb * Hh * Ss * Ss;

    __nv_bfloat16 *inqh, *inql, *inkh, *inkl, *invh, *invl;
    __nv_bfloat16 *wqh, *wql, *wkh, *wkl, *wvh, *wvl, *woh, *wol;
    __nv_bfloat16 *qh, *ql, *kh, *kl, *vh, *vl, *relh, *rell, *ctxh, *ctxl;
    cudaGetSymbolAddress((void**)&inqh, g_inqh); cudaGetSymbolAddress((void**)&inql, g_inql);
    cudaGetSymbolAddress((void**)&inkh, g_inkh); cudaGetSymbolAddress((void**)&inkl, g_inkl);
    cudaGetSymbolAddress((void**)&invh, g_invh); cudaGetSymbolAddress((void**)&invl, g_invl);
    cudaGetSymbolAddress((void**)&wqh, g_wqh);   cudaGetSymbolAddress((void**)&wql, g_wql);
    cudaGetSymbolAddress((void**)&wkh, g_wkh);   cudaGetSymbolAddress((void**)&wkl, g_wkl);
    cudaGetSymbolAddress((void**)&wvh, g_wvh);   cudaGetSymbolAddress((void**)&wvl, g_wvl);
    cudaGetSymbolAddress((void**)&woh, g_woh);   cudaGetSymbolAddress((void**)&wol, g_wol);
    cudaGetSymbolAddress((void**)&qh, g_qh);     cudaGetSymbolAddress((void**)&ql, g_ql);
    cudaGetSymbolAddress((void**)&kh, g_kh);     cudaGetSymbolAddress((void**)&kl, g_kl);
    cudaGetSymbolAddress((void**)&vh, g_vh);     cudaGetSymbolAddress((void**)&vl, g_vl);
    cudaGetSymbolAddress((void**)&relh, g_relh); cudaGetSymbolAddress((void**)&rell, g_rell);
    cudaGetSymbolAddress((void**)&ctxh, g_ctxh); cudaGetSymbolAddress((void**)&ctxl, g_ctxl);

    cudaFuncSetAttribute(proj_qkv_mma,  cudaFuncAttributeMaxDynamicSharedMemorySize, 131072);
    cudaFuncSetAttribute(outproj_mma,   cudaFuncAttributeMaxDynamicSharedMemorySize, 131072);
    cudaFuncSetAttribute(content_kernel,cudaFuncAttributeMaxDynamicSharedMemorySize, 65536);
    cudaFuncSetAttribute(pos_kernel,    cudaFuncAttributeMaxDynamicSharedMemorySize, 65536);
    cudaFuncSetAttribute(ctx_mma,       cudaFuncAttributeMaxDynamicSharedMemorySize, 49152);

    split_kernel<<<2048, 256>>>(query, inqh, inql, 524288);
    split_kernel<<<2048, 256>>>(key,   inkh, inkl, 524288);
    split_kernel<<<2048, 256>>>(value, invh, invl, 524288);
    split_kernel<<<256, 256>>>(Wq, wqh, wql, 65536);
    split_kernel<<<256, 256>>>(Wk, wkh, wkl, 65536);
    split_kernel<<<256, 256>>>(Wv, wvh, wvl, 65536);
    split_kernel<<<256, 256>>>(Wo, woh, wol, 65536);
    rel_proj_kernel<<<512, 256>>>(pos_emb, Wp, bp, relh, rell);

    proj_qkv_mma<<<dim3(4, 32), 256, 131072>>>(inqh, inql, wqh, wql, bq, qh, ql);
    proj_qkv_mma<<<dim3(4, 32), 256, 131072>>>(inkh, inkl, wkh, wkl, bk, kh, kl);
    proj_qkv_mma<<<dim3(4, 32), 256, 131072>>>(invh, invl, wvh, wvl, bv, vh, vl);

    content_kernel<<<dim3(8, 8, 32), 256, 65536>>>(qh, ql, kh, kl, csc);
    pos_kernel<<<dim3(9, 8, 32), 256, 65536>>>(qh, ql, relh, rell, psc);

    softmax_fused<<<Bb * Hh * Ss, 256>>>(csc, psc, attn);
    ctx_mma<<<dim3(8, 32), 256, 49152>>>(attn, vh, vl, ctxh, ctxl);
    outproj_mma<<<dim3(4, 32), 256, 131072>>>(ctxh, ctxl, woh, wol, bo, out);
}

// round 7
// speedup vs baseline: 2.7704x; 1.0062x over previous
#include <cuda_runtime.h>
#include <cuda_bf16.h>
#include <cstdint>

#define Bb 4
#define Ss 1024
#define Dd 512
#define Hh 8
#define DH 64
#define RR 2047
#define RPAD 2304

// ---------------- scratch (device globals; zero-init, no allocation) ------
__device__ __nv_bfloat16 g_inqh[4096*512], g_inql[4096*512];
__device__ __nv_bfloat16 g_inkh[4096*512], g_inkl[4096*512];
__device__ __nv_bfloat16 g_invh[4096*512], g_invl[4096*512];
__device__ __nv_bfloat16 g_wqh[512*512], g_wql[512*512];
__device__ __nv_bfloat16 g_wkh[512*512], g_wkl[512*512];
__device__ __nv_bfloat16 g_wvh[512*512], g_wvl[512*512];
__device__ __nv_bfloat16 g_woh[512*512], g_wol[512*512];
__device__ __nv_bfloat16 g_qh[32*1024*64], g_ql[32*1024*64];
__device__ __nv_bfloat16 g_kh[32*1024*64], g_kl[32*1024*64];
__device__ __nv_bfloat16 g_vh[32*1024*64], g_vl[32*1024*64];
__device__ __nv_bfloat16 g_relh[RPAD*64], g_rell[RPAD*64];   // rows >=2047 stay 0
__device__ __nv_bfloat16 g_ctxh[4096*512], g_ctxl[4096*512];

extern __shared__ char dsm[];

// ======================= helpers =========================================
__device__ __forceinline__ uint32_t smem_u32(const void* p) {
    uint32_t a;
    asm("{ .reg .u64 t; cvta.to.shared.u64 t, %1; cvt.u32.u64 %0, t; }"
        : "=r"(a) : "l"(p));
    return a;
}
__device__ __forceinline__ void ldsm4(uint32_t* r, uint32_t addr) {
    asm volatile("ldmatrix.sync.aligned.m8n8.x4.shared.b16 {%0,%1,%2,%3}, [%4];"
        : "=r"(r[0]), "=r"(r[1]), "=r"(r[2]), "=r"(r[3]) : "r"(addr));
}
__device__ __forceinline__ void ldsm4t(uint32_t* r, uint32_t addr) {
    asm volatile("ldmatrix.sync.aligned.m8n8.x4.trans.shared.b16 {%0,%1,%2,%3}, [%4];"
        : "=r"(r[0]), "=r"(r[1]), "=r"(r[2]), "=r"(r[3]) : "r"(addr));
}
__device__ __forceinline__ void mma16816(float* d, const uint32_t* a, const uint32_t* b) {
    asm volatile("mma.sync.aligned.m16n8k16.row.col.f32.bf16.bf16.f32 "
        "{%0,%1,%2,%3}, {%4,%5,%6,%7}, {%8,%9}, {%0,%1,%2,%3};"
        : "+f"(d[0]), "+f"(d[1]), "+f"(d[2]), "+f"(d[3])
        : "r"(a[0]), "r"(a[1]), "r"(a[2]), "r"(a[3]), "r"(b[0]), "r"(b[1]));
}
__device__ __forceinline__ void cp16(uint32_t dst, const void* src) {
    asm volatile("cp.async.cg.shared.global [%0], [%1], 16;" :: "r"(dst), "l"(src));
}
#define CP_COMMIT() asm volatile("cp.async.commit_group;" ::: "memory")
#define CP_WAIT(N)  asm volatile("cp.async.wait_group %0;" :: "n"(N) : "memory")

__device__ __forceinline__ uint32_t pack_split(float a, float b, float& ra, float& rb) {
    __nv_bfloat16 ha = __float2bfloat16_rn(a), hb = __float2bfloat16_rn(b);
    ra = a - __bfloat162float(ha);
    rb = b - __bfloat162float(hb);
    return (uint32_t)__bfloat16_as_ushort(ha) | ((uint32_t)__bfloat16_as_ushort(hb) << 16);
}
__device__ __forceinline__ uint32_t pack_bf2(float a, float b) {
    return (uint32_t)__bfloat16_as_ushort(__float2bfloat16_rn(a)) |
           ((uint32_t)__bfloat16_as_ushort(__float2bfloat16_rn(b)) << 16);
}

// ---------------- fp32 -> bf16 hi/lo split (elementwise) ------------------
__global__ __launch_bounds__(256)
void split_kernel(const float* __restrict__ in, __nv_bfloat16* __restrict__ oh,
                  __nv_bfloat16* __restrict__ ol, int n4) {
    int i = blockIdx.x * 256 + threadIdx.x;
    if (i >= n4) return;
    float4 v = reinterpret_cast<const float4*>(in)[i];
    float r0, r1, r2, r3;
    uint32_t h0 = pack_split(v.x, v.y, r0, r1);
    uint32_t h1 = pack_split(v.z, v.w, r2, r3);
    reinterpret_cast<uint2*>(oh)[i] = make_uint2(h0, h1);
    reinterpret_cast<uint2*>(ol)[i] = make_uint2(pack_bf2(r0, r1), pack_bf2(r2, r3));
}

// ====== core: 128x128 CTA tile, 3-pass bf16-split MMA, K = 64*kchunks =====
// STAGES=1: single 64KB buffer (high-grid kernels); STAGES=2: 128KB pipeline.
template<int STAGES>
__device__ __forceinline__ void mma_core_128(
    float acc[2][8][4],
    const __nv_bfloat16* __restrict__ Ah, const __nv_bfloat16* __restrict__ Al, int lda,
    const __nv_bfloat16* __restrict__ Bh, const __nv_bfloat16* __restrict__ Bl, int ldb,
    int kchunks)
{
    const uint32_t sb = smem_u32(dsm);
    int tid = threadIdx.x, lane = tid & 31, wid = tid >> 5;
    int wm = (wid & 3) << 5, wn = (wid >> 2) << 6;

    uint32_t a_row = wm + (lane & 15);
    uint32_t a_off = a_row * 128, a_sw = (a_row & 7) << 4, a_cb = lane & 16;
    uint32_t b_row = wn + (lane & 7) + ((lane >> 1) & 8);
    uint32_t b_off = b_row * 128, b_sw = (b_row & 7) << 4, b_cb = (lane & 8) << 1;

    // precompute this thread's 4 fill slots
    int fr[4], fc[4];
    #pragma unroll
    for (int l = 0; l < 4; l++) {
        int i = tid + l * 256;
        fr[l] = i >> 3; fc[l] = i & 7;
    }

    auto issue = [&](int kc, int stage) {
        uint32_t s0 = sb + stage * 65536u;
        #pragma unroll
        for (int l = 0; l < 4; l++) {
            int r = fr[l], c = fc[l];
            uint32_t doff = r * 128 + ((c * 16) ^ ((r & 7) << 4));
            size_t ga = (size_t)r * lda + kc * 64 + c * 8;
            size_t gb = (size_t)r * ldb + kc * 64 + c * 8;
            cp16(s0 + doff,          Ah + ga);
            cp16(s0 + 16384 + doff,  Al + ga);
            cp16(s0 + 32768 + doff,  Bh + gb);
            cp16(s0 + 49152 + doff,  Bl + gb);
        }
        CP_COMMIT();
    };

    issue(0, 0);
    for (int kc = 0; kc < kchunks; kc++) {
        int st = (STAGES == 2) ? (kc & 1) : 0;
        if (STAGES == 2 && kc + 1 < kchunks) {
            issue(kc + 1, (kc + 1) & 1);
            CP_WAIT(1);
        } else {
            CP_WAIT(0);
        }
        __syncthreads();
        uint32_t base = sb + st * 65536u;
        #pragma unroll
        for (int p = 0; p < 3; p++) {
            uint32_t Abase = base + (p == 2 ? 16384u : 0u);
            uint32_t Bbase = base + 32768u + (p == 1 ? 16384u : 0u);
            #pragma unroll
            for (int k = 0; k < 4; k++) {
                uint32_t a0[4], a1[4];
                uint32_t ca = (uint32_t)(k * 32) + a_cb;
                uint32_t addrA = Abase + a_off + (ca ^ a_sw);
                ldsm4(a0, addrA);
                ldsm4(a1, addrA + 16 * 128);
                uint32_t cb = (uint32_t)(k * 32) + b_cb;
                uint32_t addrB = Bbase + b_off + (cb ^ b_sw);
                uint32_t bfr[4][4];
                #pragma unroll
                for (int j = 0; j < 4; j++) ldsm4(bfr[j], addrB + j * (16 * 128));
                #pragma unroll
                for (int j = 0; j < 4; j++) {
                    mma16816(acc[0][2*j],     a0, &bfr[j][0]);
                    mma16816(acc[0][2*j + 1], a0, &bfr[j][2]);
                    mma16816(acc[1][2*j],     a1, &bfr[j][0]);
                    mma16816(acc[1][2*j + 1], a1, &bfr[j][2]);
                }
            }
        }
        if (kc + 1 < kchunks) __syncthreads();
    }
}

// ------------- content scores: csc = q @ k^T ------------------------------
__global__ __launch_bounds__(256)
void content_kernel(const __nv_bfloat16* __restrict__ qh, const __nv_bfloat16* __restrict__ ql,
                    const __nv_bfloat16* __restrict__ kh, const __nv_bfloat16* __restrict__ kl,
                    float* __restrict__ csc) {
    int bh = blockIdx.z, m0 = blockIdx.y << 7, n0 = blockIdx.x << 7;
    size_t ab = (size_t)bh * Ss * DH;
    float acc[2][8][4] = {};
    mma_core_128<1>(acc, qh + ab + (size_t)m0 * DH, ql + ab + (size_t)m0 * DH, DH,
                    kh + ab + (size_t)n0 * DH, kl + ab + (size_t)n0 * DH, DH, 1);
    int lane = threadIdx.x & 31, wid = threadIdx.x >> 5;
    int er = ((wid & 3) << 5) + (lane >> 2);
    int ec = ((wid >> 2) << 6) + ((lane & 3) << 1);
    float* out = csc + ((size_t)bh * Ss + m0) * Ss + n0;
    #pragma unroll
    for (int mi = 0; mi < 2; mi++)
        #pragma unroll
        for (int j = 0; j < 8; j++) {
            int r = er + mi * 16, c = ec + j * 8;
            *reinterpret_cast<float2*>(&out[(size_t)r * Ss + c]) =
                make_float2(acc[mi][j][0], acc[mi][j][1]);
            *reinterpret_cast<float2*>(&out[(size_t)(r + 8) * Ss + c]) =
                make_float2(acc[mi][j][2], acc[mi][j][3]);
        }
}

// ------ pos scores with fused skew: psc[s][t] = q[s]·rel[t-s+1023] --------
// GEMM over window u; epilogue scatters u -> t = u + sl - 127 (predicated).
__global__ __launch_bounds__(256)
void pos_kernel(const __nv_bfloat16* __restrict__ qh, const __nv_bfloat16* __restrict__ ql,
                const __nv_bfloat16* __restrict__ relh, const __nv_bfloat16* __restrict__ rell,
                float* __restrict__ psc) {
    int bh = blockIdx.z, sblk = blockIdx.y, u0 = blockIdx.x << 7;
    int s0 = sblk << 7;
    int rb = 896 - s0 + u0;                       // rel row for u-local 0
    size_t ab = (size_t)bh * Ss * DH;
    float acc[2][8][4] = {};
    mma_core_128<1>(acc, qh + ab + (size_t)s0 * DH, ql + ab + (size_t)s0 * DH, DH,
                    relh + (size_t)rb * DH, rell + (size_t)rb * DH, DH, 1);
    int lane = threadIdx.x & 31, wid = threadIdx.x >> 5;
    int er = ((wid & 3) << 5) + (lane >> 2);
    int ec = ((wid >> 2) << 6) + ((lane & 3) << 1);
    float* pbase = psc + ((size_t)bh * Ss + s0) * Ss;
    #pragma unroll
    for (int mi = 0; mi < 2; mi++)
        #pragma unroll
        for (int j = 0; j < 8; j++) {
            int u = u0 + ec + j * 8;
            #pragma unroll
            for (int hf = 0; hf < 2; hf++) {
                int sl = er + mi * 16 + hf * 8;
                int t = u + sl - 127;
                float v0 = acc[mi][j][hf*2], v1 = acc[mi][j][hf*2+1];
                if ((unsigned)t < 1024u)       pbase[(size_t)sl * Ss + t] = v0;
                if ((unsigned)(t + 1) < 1024u) pbase[(size_t)sl * Ss + t + 1] = v1;
            }
        }
}

// ------ q/k/v projection: x @ W^T + b -> permuted bf16 hi/lo [bh][s][d] ---
__global__ __launch_bounds__(256)
void proj_qkv_mma(const __nv_bfloat16* __restrict__ xh, const __nv_bfloat16* __restrict__ xl,
                  const __nv_bfloat16* __restrict__ wh, const __nv_bfloat16* __restrict__ wl,
                  const float* __restrict__ bias,
                  __nv_bfloat16* __restrict__ oh, __nv_bfloat16* __restrict__ ol) {
    int n0 = blockIdx.x << 7, m0 = blockIdx.y << 7;
    float acc[2][8][4] = {};
    mma_core_128<2>(acc, xh + (size_t)m0 * Dd, xl + (size_t)m0 * Dd, Dd,
                    wh + (size_t)n0 * Dd, wl + (size_t)n0 * Dd, Dd, 8);
    int lane = threadIdx.x & 31, wid = threadIdx.x >> 5;
    int er = ((wid & 3) << 5) + (lane >> 2);
    int ec = ((wid >> 2) << 6) + ((lane & 3) << 1);
    #pragma unroll
    for (int mi = 0; mi < 2; mi++)
        #pragma unroll
        for (int j = 0; j < 8; j++) {
            int c = n0 + ec + j * 8;
            float b0 = bias[c], b1 = bias[c + 1];
            #pragma unroll
            for (int hf = 0; hf < 2; hf++) {
                int m = m0 + er + mi * 16 + hf * 8;
                float v0 = acc[mi][j][hf*2] + b0, v1 = acc[mi][j][hf*2+1] + b1;
                int b = m >> 10, s = m & 1023;
                int h = c >> 6, d = c & 63;
                size_t off = ((size_t)((((b << 3) | h) << 10) | s)) * DH + d;
                float r0, r1;
                uint32_t hv = pack_split(v0, v1, r0, r1);
                *reinterpret_cast<uint32_t*>(&oh[off]) = hv;
                *reinterpret_cast<uint32_t*>(&ol[off]) = pack_bf2(r0, r1);
            }
        }
}

// ------ output projection: ctx @ Wo^T + bo -> fp32 [4096][512] ------------
__global__ __launch_bounds__(256)
void outproj_mma(const __nv_bfloat16* __restrict__ xh, const __nv_bfloat16* __restrict__ xl,
                 const __nv_bfloat16* __restrict__ wh, const __nv_bfloat16* __restrict__ wl,
                 const float* __restrict__ bias, float* __restrict__ out) {
    int n0 = blockIdx.x << 7, m0 = blockIdx.y << 7;
    float acc[2][8][4] = {};
    mma_core_128<2>(acc, xh + (size_t)m0 * Dd, xl + (size_t)m0 * Dd, Dd,
                    wh + (size_t)n0 * Dd, wl + (size_t)n0 * Dd, Dd, 8);
    int lane = threadIdx.x & 31, wid = threadIdx.x >> 5;
    int er = ((wid & 3) << 5) + (lane >> 2);
    int ec = ((wid >> 2) << 6) + ((lane & 3) << 1);
    #pragma unroll
    for (int mi = 0; mi < 2; mi++)
        #pragma unroll
        for (int j = 0; j < 8; j++) {
            int c = n0 + ec + j * 8;
            float b0 = bias[c], b1 = bias[c + 1];
            int m = m0 + er + mi * 16;
            *reinterpret_cast<float2*>(&out[(size_t)m * Dd + c]) =
                make_float2(acc[mi][j][0] + b0, acc[mi][j][1] + b1);
            *reinterpret_cast<float2*>(&out[(size_t)(m + 8) * Dd + c]) =
                make_float2(acc[mi][j][2] + b0, acc[mi][j][3] + b1);
        }
}

// ---------------- rel projection: rel = pos_emb @ Wp^T + bp ---------------
__global__ __launch_bounds__(256)
void rel_proj_kernel(const float* __restrict__ P, const float* __restrict__ Wp,
                     const float* __restrict__ bp,
                     __nv_bfloat16* __restrict__ oh, __nv_bfloat16* __restrict__ ol) {
    __shared__ float sWT[64 * 64];
    __shared__ float sP[4][64];
    int tid = threadIdx.x;
    for (int i = tid; i < 4096; i += 256) {
        int d = i >> 6, c = i & 63;
        sWT[c * 64 + d] = Wp[i];
    }
    int g = tid >> 6, d = tid & 63;
    int r = blockIdx.x * 4 + g;
    sP[g][d] = (r < RR) ? P[r * 64 + d] : 0.f;
    __syncthreads();
    float acc = bp[d];
    #pragma unroll 16
    for (int c = 0; c < 64; c++) acc += sP[g][c] * sWT[c * 64 + d];
    if (r < RR) {
        __nv_bfloat16 h = __float2bfloat16_rn(acc);
        oh[r * 64 + d] = h;
        ol[r * 64 + d] = __float2bfloat16_rn(acc - __bfloat162float(h));
    }
}

// ------- softmax over (csc+psc)/sqrt(512): writes attn --------------------
__global__ __launch_bounds__(256)
void softmax_fused(const float* __restrict__ csc, const float* __restrict__ psc,
                   float* __restrict__ attn) {
    const float scl = 0.04419417382415922f;   // 1/sqrt(512)
    size_t base = (size_t)blockIdx.x * Ss;
    int tid = threadIdx.x, t0 = tid * 4;

    float4 cv = *reinterpret_cast<const float4*>(csc + base + t0);
    float4 pv = *reinterpret_cast<const float4*>(psc + base + t0);
    float s0 = (cv.x + pv.x) * scl, s1 = (cv.y + pv.y) * scl;
    float s2 = (cv.z + pv.z) * scl, s3 = (cv.w + pv.w) * scl;

    float m = fmaxf(fmaxf(s0, s1), fmaxf(s2, s3));
    #pragma unroll
    for (int o = 16; o; o >>= 1) m = fmaxf(m, __shfl_xor_sync(0xffffffffu, m, o));
    __shared__ float red[8];
    int wid = tid >> 5, lid = tid & 31;
    if (lid == 0) red[wid] = m;
    __syncthreads();
    m = red[0];
    #pragma unroll
    for (int w = 1; w < 8; w++) m = fmaxf(m, red[w]);

    float e0 = __expf(s0 - m), e1 = __expf(s1 - m);
    float e2 = __expf(s2 - m), e3 = __expf(s3 - m);
    float sum = (e0 + e1) + (e2 + e3);
    #pragma unroll
    for (int o = 16; o; o >>= 1) sum += __shfl_xor_sync(0xffffffffu, sum, o);
    __syncthreads();
    if (lid == 0) red[wid] = sum;
    __syncthreads();
    float tot = red[0];
    #pragma unroll
    for (int w = 1; w < 8; w++) tot += red[w];
    float inv = 1.0f / tot;

    *reinterpret_cast<float4*>(&attn[base + t0]) =
        make_float4(e0 * inv, e1 * inv, e2 * inv, e3 * inv);
}

// ------ ctx = attn @ v (split on the fly) -> bf16 hi/lo [b][s][h*64+d] ----
__global__ __launch_bounds__(256)
void ctx_mma(const float* __restrict__ attn,
             const __nv_bfloat16* __restrict__ vh, const __nv_bfloat16* __restrict__ vl,
             __nv_bfloat16* __restrict__ ch, __nv_bfloat16* __restrict__ cl) {
    char* sAh = dsm;           char* sAl = dsm + 16384;
    char* sVh = dsm + 32768;   char* sVl = dsm + 40960;
    const uint32_t sb = smem_u32(dsm);
    int bh = blockIdx.y, s0 = blockIdx.x << 7;
    const float* ab = attn + ((size_t)bh * Ss + s0) * Ss;
    const __nv_bfloat16* vhb = vh + (size_t)bh * Ss * DH;
    const __nv_bfloat16* vlb = vl + (size_t)bh * Ss * DH;
    int tid = threadIdx.x, lane = tid & 31, wid = tid >> 5;
    int wm = (wid & 3) << 5, wn = (wid >> 2) << 5;

    uint32_t a_row = wm + (lane & 15);
    uint32_t a_off = a_row * 128, a_sw = (a_row & 7) << 4, a_cb = lane & 16;
    uint32_t bt = (lane & 7) + (lane & 8);       // t within k16 step
    uint32_t b_cb16 = lane & 16;

    float acc[2][4][4] = {};
    for (int kc = 0; kc < 16; kc++) {
        if (kc) __syncthreads();
        // V tiles via cp.async, overlapped under the attn convert/fill below
        #pragma unroll
        for (int l = 0; l < 2; l++) {
            int i = tid + l * 256;
            int r = i >> 3, c = i & 7;
            uint32_t doff = r * 128 + ((c * 16) ^ ((r & 7) << 4));
            size_t g = (size_t)(kc * 64 + r) * DH + c * 8;
            cp16(sb + 32768 + doff, vhb + g);
            cp16(sb + 40960 + doff, vlb + g);
        }
        CP_COMMIT();
        #pragma unroll
        for (int l = 0; l < 8; l++) {            // 2048 float4 of attn
            int i = tid + l * 256;
            int r = i >> 4, c = i & 15;
            float4 v = *reinterpret_cast<const float4*>(ab + (size_t)r * Ss + kc * 64 + c * 4);
            float r0, r1, r2, r3;
            uint32_t h0 = pack_split(v.x, v.y, r0, r1);
            uint32_t h1 = pack_split(v.z, v.w, r2, r3);
            uint32_t doff = r * 128 + ((c * 8) ^ ((r & 7) << 4));
            *reinterpret_cast<uint2*>(sAh + doff) = make_uint2(h0, h1);
            *reinterpret_cast<uint2*>(sAl + doff) = make_uint2(pack_bf2(r0, r1), pack_bf2(r2, r3));
        }
        CP_WAIT(0);
        __syncthreads();
        #pragma unroll
        for (int p = 0; p < 3; p++) {
            uint32_t Abase = sb + (p == 2 ? 16384u : 0u);
            uint32_t Vbase = sb + (p == 1 ? 40960u : 32768u);
            #pragma unroll
            for (int k = 0; k < 4; k++) {
                uint32_t a0[4], a1[4];
                uint32_t ca = (uint32_t)(k * 32) + a_cb;
                uint32_t addrA = Abase + a_off + (ca ^ a_sw);
                ldsm4(a0, addrA);
                ldsm4(a1, addrA + 16 * 128);
                uint32_t bfr[2][4];
                #pragma unroll
                for (int l2 = 0; l2 < 2; l2++) {
                    uint32_t t = (uint32_t)(k * 16) + bt;
                    uint32_t cb = (uint32_t)((wn + l2 * 16) * 2) + b_cb16;
                    uint32_t addrB = Vbase + t * 128 + (cb ^ ((t & 7) << 4));
                    ldsm4t(bfr[l2], addrB);
                }
                #pragma unroll
                for (int j = 0; j < 4; j++) {
                    const uint32_t* bb = (j & 1) ? &bfr[j >> 1][2] : &bfr[j >> 1][0];
                    mma16816(acc[0][j], a0, bb);
                    mma16816(acc[1][j], a1, bb);
                }
            }
        }
    }
    int b = bh >> 3, h = bh & 7;
    int er = wm + (lane >> 2), ec = wn + ((lane & 3) << 1);
    #pragma unroll
    for (int mi = 0; mi < 2; mi++)
        #pragma unroll
        for (int j = 0; j < 4; j++)
            #pragma unroll
            for (int hf = 0; hf < 2; hf++) {
                int s = s0 + er + mi * 16 + hf * 8;
                int d = ec + j * 8;
                float v0 = acc[mi][j][hf*2], v1 = acc[mi][j][hf*2+1];
                size_t off = ((size_t)((b << 10) | s)) * Dd + (h << 6) + d;
                float r0, r1;
                uint32_t hv = pack_split(v0, v1, r0, r1);
                *reinterpret_cast<uint32_t*>(&ch[off]) = hv;
                *reinterpret_cast<uint32_t*>(&cl[off]) = pack_bf2(r0, r1);
            }
}

// -------------------------------------------------------------------------
extern "C" void kernel_launch(void* const* d_in, const int* in_sizes, int n_in,
                              void* d_out, int out_size) {
    const float* query   = (const float*)d_in[0];
    const float* key     = (const float*)d_in[1];
    const float* value   = (const float*)d_in[2];
    const float* pos_emb = (const float*)d_in[3];
    const float* Wq = (const float*)d_in[4];
    const float* bq = (const float*)d_in[5];
    const float* Wk = (const float*)d_in[6];
    const float* bk = (const float*)d_in[7];
    const float* Wv = (const float*)d_in[8];
    const float* bv = (const float*)d_in[9];
    const float* Wo = (const float*)d_in[10];
    const float* bo = (const float*)d_in[11];
    const float* Wp = (const float*)d_in[12];
    const float* bp = (const float*)d_in[13];

    float* out  = (float*)d_out;
    float* attn = out  + (size_t)Bb * Ss * Dd;
    float* csc  = attn + (size_t)Bb * Hh * Ss * Ss;
    float* psc  = csc  + (size_t)Bb * Hh * Ss * Ss;

    __nv_bfloat16 *inqh, *inql, *inkh, *inkl, *invh, *invl;
    __nv_bfloat16 *wqh, *wql, *wkh, *wkl, *wvh, *wvl, *woh, *wol;
    __nv_bfloat16 *qh, *ql, *kh, *kl, *vh, *vl, *relh, *rell, *ctxh, *ctxl;
    cudaGetSymbolAddress((void**)&inqh, g_inqh); cudaGetSymbolAddress((void**)&inql, g_inql);
    cudaGetSymbolAddress((void**)&inkh, g_inkh); cudaGetSymbolAddress((void**)&inkl, g_inkl);
    cudaGetSymbolAddress((void**)&invh, g_invh); cudaGetSymbolAddress((void**)&invl, g_invl);
    cudaGetSymbolAddress((void**)&wqh, g_wqh);   cudaGetSymbolAddress((void**)&wql, g_wql);
    cudaGetSymbolAddress((void**)&wkh, g_wkh);   cudaGetSymbolAddress((void**)&wkl, g_wkl);
    cudaGetSymbolAddress((void**)&wvh, g_wvh);   cudaGetSymbolAddress((void**)&wvl, g_wvl);
    cudaGetSymbolAddress((void**)&woh, g_woh);   cudaGetSymbolAddress((void**)&wol, g_wol);
    cudaGetSymbolAddress((void**)&qh, g_qh);     cudaGetSymbolAddress((void**)&ql, g_ql);
    cudaGetSymbolAddress((void**)&kh, g_kh);     cudaGetSymbolAddress((void**)&kl, g_kl);
    cudaGetSymbolAddress((void**)&vh, g_vh);     cudaGetSymbolAddress((void**)&vl, g_vl);
    cudaGetSymbolAddress((void**)&relh, g_relh); cudaGetSymbolAddress((void**)&rell, g_rell);
    cudaGetSymbolAddress((void**)&ctxh, g_ctxh); cudaGetSymbolAddress((void**)&ctxl, g_ctxl);

    cudaFuncSetAttribute(proj_qkv_mma,  cudaFuncAttributeMaxDynamicSharedMemorySize, 131072);
    cudaFuncSetAttribute(outproj_mma,   cudaFuncAttributeMaxDynamicSharedMemorySize, 131072);
    cudaFuncSetAttribute(content_kernel,cudaFuncAttributeMaxDynamicSharedMemorySize, 65536);
    cudaFuncSetAttribute(pos_kernel,    cudaFuncAttributeMaxDynamicSharedMemorySize, 65536);
    cudaFuncSetAttribute(ctx_mma,       cudaFuncAttributeMaxDynamicSharedMemorySize, 49152);

    split_kernel<<<2048, 256>>>(query, inqh, inql, 524288);
    split_kernel<<<2048, 256>>>(key,   inkh, inkl, 524288);
    split_kernel<<<2048, 256>>>(value, invh, invl, 524288);
    split_kernel<<<256, 256>>>(Wq, wqh, wql, 65536);
    split_kernel<<<256, 256>>>(Wk, wkh, wkl, 65536);
    split_kernel<<<256, 256>>>(Wv, wvh, wvl, 65536);
    split_kernel<<<256, 256>>>(Wo, woh, wol, 65536);
    rel_proj_kernel<<<512, 256>>>(pos_emb, Wp, bp, relh, rell);

    proj_qkv_mma<<<dim3(4, 32), 256, 131072>>>(inqh, inql, wqh, wql, bq, qh, ql);
    proj_qkv_mma<<<dim3(4, 32), 256, 131072>>>(inkh, inkl, wkh, wkl, bk, kh, kl);
    proj_qkv_mma<<<dim3(4, 32), 256, 131072>>>(invh, invl, wvh, wvl, bv, vh, vl);

    content_kernel<<<dim3(8, 8, 32), 256, 65536>>>(qh, ql, kh, kl, csc);
    pos_kernel<<<dim3(9, 8, 32), 256, 65536>>>(qh, ql, relh, rell, psc);

    softmax_fused<<<Bb * Hh * Ss, 256>>>(csc, psc, attn);
    ctx_mma<<<dim3(8, 32), 256, 49152>>>(attn, vh, vl, ctxh, ctxl);
    outproj_mma<<<dim3(4, 32), 256, 131072>>>(ctxh, ctxl, woh, wol, bo, out);
}

// round 8
// speedup vs baseline: 2.7841x; 1.0049x over previous
#include <cuda_runtime.h>
#include <cuda_bf16.h>
#include <cstdint>

#define Bb 4
#define Ss 1024
#define Dd 512
#define Hh 8
#define DH 64
#define RR 2047
#define RPAD 2304

__device__ __nv_bfloat16 g_inqh[4096*512], g_inql[4096*512];
__device__ __nv_bfloat16 g_inkh[4096*512], g_inkl[4096*512];
__device__ __nv_bfloat16 g_invh[4096*512], g_invl[4096*512];
__device__ __nv_bfloat16 g_wqh[512*512], g_wql[512*512];
__device__ __nv_bfloat16 g_wkh[512*512], g_wkl[512*512];
__device__ __nv_bfloat16 g_wvh[512*512], g_wvl[512*512];
__device__ __nv_bfloat16 g_woh[512*512], g_wol[512*512];
__device__ __nv_bfloat16 g_qh[32*1024*64], g_ql[32*1024*64];
__device__ __nv_bfloat16 g_kh[32*1024*64], g_kl[32*1024*64];
__device__ __nv_bfloat16 g_vh[32*1024*64], g_vl[32*1024*64];
__device__ __nv_bfloat16 g_relh[RPAD*64], g_rell[RPAD*64];
__device__ __nv_bfloat16 g_ctxh[4096*512], g_ctxl[4096*512];
__device__ float         g_rowsum[32*1024];

extern __shared__ char dsm[];

__device__ __forceinline__ uint32_t smem_u32(const void* p) {
    uint32_t a;
    asm("{ .reg .u64 t; cvta.to.shared.u64 t, %1; cvt.u32.u64 %0, t; }" : "=r"(a) : "l"(p));
    return a;
}
__device__ __forceinline__ void ldsm4(uint32_t* r, uint32_t a) {
    asm volatile("ldmatrix.sync.aligned.m8n8.x4.shared.b16 {%0,%1,%2,%3}, [%4];"
        : "=r"(r[0]), "=r"(r[1]), "=r"(r[2]), "=r"(r[3]) : "r"(a));
}
__device__ __forceinline__ void ldsm4t(uint32_t* r, uint32_t a) {
    asm volatile("ldmatrix.sync.aligned.m8n8.x4.trans.shared.b16 {%0,%1,%2,%3}, [%4];"
        : "=r"(r[0]), "=r"(r[1]), "=r"(r[2]), "=r"(r[3]) : "r"(a));
}
__device__ __forceinline__ void mma16816(float* d, const uint32_t* a, const uint32_t* b) {
    asm volatile("mma.sync.aligned.m16n8k16.row.col.f32.bf16.bf16.f32 "
        "{%0,%1,%2,%3}, {%4,%5,%6,%7}, {%8,%9}, {%0,%1,%2,%3};"
        : "+f"(d[0]), "+f"(d[1]), "+f"(d[2]), "+f"(d[3])
        : "r"(a[0]), "r"(a[1]), "r"(a[2]), "r"(a[3]), "r"(b[0]), "r"(b[1]));
}
__device__ __forceinline__ void cp16(uint32_t dst, const void* src) {
    asm volatile("cp.async.cg.shared.global [%0], [%1], 16;" :: "r"(dst), "l"(src));
}
#define CP_COMMIT() asm volatile("cp.async.commit_group;" ::: "memory")
#define CP_WAIT(N)  asm volatile("cp.async.wait_group %0;" :: "n"(N) : "memory")

__device__ __forceinline__ uint32_t pack_split(float a, float b, float& ra, float& rb) {
    __nv_bfloat16 ha = __float2bfloat16_rn(a), hb = __float2bfloat16_rn(b);
    ra = a - __bfloat162float(ha);
    rb = b - __bfloat162float(hb);
    return (uint32_t)__bfloat16_as_ushort(ha) | ((uint32_t)__bfloat16_as_ushort(hb) << 16);
}
__device__ __forceinline__ uint32_t pack_bf2(float a, float b) {
    return (uint32_t)__bfloat16_as_ushort(__float2bfloat16_rn(a)) |
           ((uint32_t)__bfloat16_as_ushort(__float2bfloat16_rn(b)) << 16);
}

// ---------- merged 7-tensor fp32 -> bf16 hi/lo split (one launch) ---------
__global__ __launch_bounds__(256)
void split_all(const float* q, const float* k, const float* v,
               const float* Wq, const float* Wk, const float* Wv, const float* Wo,
               __nv_bfloat16* qhh, __nv_bfloat16* qll, __nv_bfloat16* khh, __nv_bfloat16* kll,
               __nv_bfloat16* vhh, __nv_bfloat16* vll,
               __nv_bfloat16* wqh, __nv_bfloat16* wql, __nv_bfloat16* wkh, __nv_bfloat16* wkl,
               __nv_bfloat16* wvh, __nv_bfloat16* wvl, __nv_bfloat16* woh, __nv_bfloat16* wol) {
    int gb = blockIdx.x;
    const float* in; __nv_bfloat16 *oh, *ol; int i;
    if (gb < 6144) {
        int w = gb >> 11; i = (gb & 2047) * 256 + threadIdx.x;
        in = w == 0 ? q : w == 1 ? k : v;
        oh = w == 0 ? qhh : w == 1 ? khh : vhh;
        ol = w == 0 ? qll : w == 1 ? kll : vll;
    } else {
        int w = (gb - 6144) >> 8; i = ((gb - 6144) & 255) * 256 + threadIdx.x;
        in = w == 0 ? Wq : w == 1 ? Wk : w == 2 ? Wv : Wo;
        oh = w == 0 ? wqh : w == 1 ? wkh : w == 2 ? wvh : woh;
        ol = w == 0 ? wql : w == 1 ? wkl : w == 2 ? wvl : wol;
    }
    float4 val = reinterpret_cast<const float4*>(in)[i];
    float r0, r1, r2, r3;
    uint32_t h0 = pack_split(val.x, val.y, r0, r1);
    uint32_t h1 = pack_split(val.z, val.w, r2, r3);
    reinterpret_cast<uint2*>(oh)[i] = make_uint2(h0, h1);
    reinterpret_cast<uint2*>(ol)[i] = make_uint2(pack_bf2(r0, r1), pack_bf2(r2, r3));
}

// ---- shared 48-MMA step: A hi/lo at aBase/aBase+16K, B at bBase/+16K ----
__device__ __forceinline__ void mma_step48(float acc[2][8][4], uint32_t aBase, uint32_t bBase,
                                           uint32_t a_off, uint32_t a_sw, uint32_t a_cb,
                                           uint32_t b_off, uint32_t b_sw, uint32_t b_cb) {
    #pragma unroll
    for (int k = 0; k < 4; k++) {
        uint32_t aA = aBase + a_off + (((uint32_t)(k * 32) + a_cb) ^ a_sw);
        uint32_t ah0[4], ah1[4], al0[4], al1[4];
        ldsm4(ah0, aA); ldsm4(ah1, aA + 2048);
        ldsm4(al0, aA + 16384); ldsm4(al1, aA + 16384 + 2048);
        uint32_t bA = bBase + b_off + (((uint32_t)(k * 32) + b_cb) ^ b_sw);
        uint32_t bh[4][4], bl[4][4];
        #pragma unroll
        for (int j = 0; j < 4; j++) { ldsm4(bh[j], bA + j * 2048); ldsm4(bl[j], bA + 16384 + j * 2048); }
        #pragma unroll
        for (int j = 0; j < 4; j++) {
            mma16816(acc[0][2*j],   ah0, &bh[j][0]); mma16816(acc[0][2*j+1], ah0, &bh[j][2]);
            mma16816(acc[1][2*j],   ah1, &bh[j][0]); mma16816(acc[1][2*j+1], ah1, &bh[j][2]);
            mma16816(acc[0][2*j],   ah0, &bl[j][0]); mma16816(acc[0][2*j+1], ah0, &bl[j][2]);
            mma16816(acc[1][2*j],   ah1, &bl[j][0]); mma16816(acc[1][2*j+1], ah1, &bl[j][2]);
            mma16816(acc[0][2*j],   al0, &bh[j][0]); mma16816(acc[0][2*j+1], al0, &bh[j][2]);
            mma16816(acc[1][2*j],   al1, &bh[j][0]); mma16816(acc[1][2*j+1], al1, &bh[j][2]);
        }
    }
}

// ====== generic K-chunked 128x128 GEMM (2-stage cp.async pipeline) ========
__device__ __forceinline__ void mma_core_128(
    float acc[2][8][4],
    const __nv_bfloat16* Ah, const __nv_bfloat16* Al, int lda,
    const __nv_bfloat16* Bh, const __nv_bfloat16* Bl, int ldb, int kchunks)
{
    const uint32_t sb = smem_u32(dsm);
    int tid = threadIdx.x, lane = tid & 31, wid = tid >> 5;
    int wm = (wid & 3) << 5, wn = (wid >> 2) << 6;
    uint32_t a_row = wm + (lane & 15);
    uint32_t a_off = a_row * 128, a_sw = (a_row & 7) << 4, a_cb = lane & 16;
    uint32_t b_row = wn + (lane & 7) + ((lane >> 1) & 8);
    uint32_t b_off = b_row * 128, b_sw = (b_row & 7) << 4, b_cb = (lane & 8) << 1;

    auto issue = [&](int kc, int stage) {
        uint32_t s0 = sb + stage * 65536u;
        #pragma unroll
        for (int l = 0; l < 4; l++) {
            int i = tid + l * 256, r = i >> 3, c = i & 7;
            uint32_t doff = r * 128 + ((c * 16) ^ ((r & 7) << 4));
            size_t ga = (size_t)r * lda + kc * 64 + c * 8;
            size_t gb = (size_t)r * ldb + kc * 64 + c * 8;
            cp16(s0 + doff, Ah + ga); cp16(s0 + 16384 + doff, Al + ga);
            cp16(s0 + 32768 + doff, Bh + gb); cp16(s0 + 49152 + doff, Bl + gb);
        }
        CP_COMMIT();
    };

    issue(0, 0);
    for (int kc = 0; kc < kchunks; kc++) {
        if (kc + 1 < kchunks) { issue(kc + 1, (kc + 1) & 1); CP_WAIT(1); }
        else CP_WAIT(0);
        __syncthreads();
        uint32_t base = sb + (kc & 1) * 65536u;
        mma_step48(acc, base, base + 32768, a_off, a_sw, a_cb, b_off, b_sw, b_cb);
        if (kc + 1 < kchunks) __syncthreads();
    }
}

// ===== MEGA: content + pos(shifted) + exp + rowsum per (bh, sblk) =========
#define PS_OFF 65536
#define RS_OFF (PS_OFF + 133120)
#define SMEM_SCORES (RS_OFF + 1024)

__global__ __launch_bounds__(256)
void scores_fused(const __nv_bfloat16* qh_g, const __nv_bfloat16* ql_g,
                  const __nv_bfloat16* kh_g, const __nv_bfloat16* kl_g,
                  const __nv_bfloat16* relh, const __nv_bfloat16* rell,
                  float* __restrict__ csc, float* __restrict__ psc,
                  float* __restrict__ eb, float* __restrict__ rowsum_g)
{
    const uint32_t sb = smem_u32(dsm);
    float* p_sh = reinterpret_cast<float*>(dsm + PS_OFF);     // [128][260]
    float* rsum = reinterpret_cast<float*>(dsm + RS_OFF);     // [2][128]
    int tid = threadIdx.x, lane = tid & 31, wid = tid >> 5;
    int wm = (wid & 3) << 5, wn = (wid >> 2) << 6;
    int sblk = blockIdx.x, bh = blockIdx.y, s0 = sblk << 7;

    uint32_t a_row = wm + (lane & 15);
    uint32_t a_off = a_row * 128, a_sw = (a_row & 7) << 4, a_cb = lane & 16;
    uint32_t b_row = wn + (lane & 7) + ((lane >> 1) & 8);
    uint32_t b_off = b_row * 128, b_sw = (b_row & 7) << 4, b_cb = (lane & 8) << 1;

    if (tid < 256) rsum[tid] = 0.f;

    const __nv_bfloat16* qhb = qh_g + ((size_t)bh * Ss + s0) * DH;
    const __nv_bfloat16* qlb = ql_g + ((size_t)bh * Ss + s0) * DH;
    #pragma unroll
    for (int l = 0; l < 4; l++) {
        int i = tid + l * 256, r = i >> 3, c = i & 7;
        uint32_t doff = r * 128 + ((c * 16) ^ ((r & 7) << 4));
        cp16(sb + doff, qhb + (size_t)r * 64 + c * 8);
        cp16(sb + 16384 + doff, qlb + (size_t)r * 64 + c * 8);
    }
    CP_COMMIT();

    const __nv_bfloat16* khb = kh_g + (size_t)bh * Ss * DH;
    const __nv_bfloat16* klb = kl_g + (size_t)bh * Ss * DH;

    auto loadB = [&](const __nv_bfloat16* BH, const __nv_bfloat16* BL) {
        #pragma unroll
        for (int l = 0; l < 4; l++) {
            int i = tid + l * 256, r = i >> 3, c = i & 7;
            uint32_t doff = r * 128 + ((c * 16) ^ ((r & 7) << 4));
            cp16(sb + 32768 + doff, BH + (size_t)r * 64 + c * 8);
            cp16(sb + 49152 + doff, BL + (size_t)r * 64 + c * 8);
        }
        CP_COMMIT();
    };

    float acc[2][8][4];
    auto gemm = [&]() {
        #pragma unroll
        for (int mi = 0; mi < 2; mi++)
            #pragma unroll
            for (int jj = 0; jj < 8; jj++)
                #pragma unroll
                for (int x = 0; x < 4; x++) acc[mi][jj][x] = 0.f;
        mma_step48(acc, sb, sb + 32768, a_off, a_sw, a_cb, b_off, b_sw, b_cb);
    };

    int er_ = wm + (lane >> 2), ec_ = wn + ((lane & 3) << 1);

    auto scatter = [&](int ju) {
        #pragma unroll
        for (int mi = 0; mi < 2; mi++)
            #pragma unroll
            for (int jj = 0; jj < 8; jj++) {
                int u = ju * 128 + ec_ + jj * 8;
                #pragma unroll
                for (int hf = 0; hf < 2; hf++) {
                    int r = er_ + mi * 16 + hf * 8;
                    int t = u + r - 127;
                    if ((unsigned)t < 1024u)       p_sh[r * 260 + (t & 255)] = acc[mi][jj][hf * 2];
                    if ((unsigned)(t + 1) < 1024u) p_sh[r * 260 + ((t + 1) & 255)] = acc[mi][jj][hf * 2 + 1];
                }
            }
    };

    loadB(relh + (size_t)(896 - s0) * 64, rell + (size_t)(896 - s0) * 64);
    CP_WAIT(0); __syncthreads();
    gemm();                   // pos u-tile 0
    __syncthreads();
    scatter(0);

    const float scl = 0.04419417382415922f;
    size_t prow = (size_t)bh * Ss + s0;
    int grp = wid >> 2;

    for (int j = 0; j < 8; j++) {
        int rb = 896 - s0 + (j + 1) * 128;
        loadB(relh + (size_t)rb * 64, rell + (size_t)rb * 64);
        CP_WAIT(0); __syncthreads();
        gemm();               // pos u-tile j+1
        __syncthreads();
        loadB(khb + (size_t)(j * 128) * 64, klb + (size_t)(j * 128) * 64);
        scatter(j + 1);
        CP_WAIT(0); __syncthreads();
        gemm();               // content tile j

        #pragma unroll
        for (int l = 0; l < 16; l++) {     // coalesced psc tile write
            int i = tid + l * 256, r = i >> 5, c4 = i & 31;
            float4 v = *reinterpret_cast<float4*>(&p_sh[r * 260 + ((j & 1) * 128) + c4 * 4]);
            *reinterpret_cast<float4*>(&psc[(prow + r) * Ss + j * 128 + c4 * 4]) = v;
        }

        float rs0 = 0.f, rs1 = 0.f, rs2 = 0.f, rs3 = 0.f;
        #pragma unroll
        for (int mi = 0; mi < 2; mi++)
            #pragma unroll
            for (int jj = 0; jj < 8; jj++) {
                int tb = j * 128 + ec_ + jj * 8;
                int sc = (j & 1) * 128 + ec_ + jj * 8;
                int r0 = er_ + mi * 16, r1 = r0 + 8;
                float2 p0 = *reinterpret_cast<float2*>(&p_sh[r0 * 260 + sc]);
                float2 p1 = *reinterpret_cast<float2*>(&p_sh[r1 * 260 + sc]);
                float c0 = acc[mi][jj][0], c1 = acc[mi][jj][1];
                float c2 = acc[mi][jj][2], c3 = acc[mi][jj][3];
                size_t o0 = (prow + r0) * Ss + tb, o1 = (prow + r1) * Ss + tb;
                *reinterpret_cast<float2*>(&csc[o0]) = make_float2(c0, c1);
                *reinterpret_cast<float2*>(&csc[o1]) = make_float2(c2, c3);
                float e00 = __expf((c0 + p0.x) * scl), e01 = __expf((c1 + p0.y) * scl);
                float e10 = __expf((c2 + p1.x) * scl), e11 = __expf((c3 + p1.y) * scl);
                *reinterpret_cast<float2*>(&eb[o0]) = make_float2(e00, e01);
                *reinterpret_cast<float2*>(&eb[o1]) = make_float2(e10, e11);
                if (mi == 0) { rs0 += e00 + e01; rs1 += e10 + e11; }
                else         { rs2 += e00 + e01; rs3 += e10 + e11; }
            }
        rs0 += __shfl_xor_sync(~0u, rs0, 1); rs0 += __shfl_xor_sync(~0u, rs0, 2);
        rs1 += __shfl_xor_sync(~0u, rs1, 1); rs1 += __shfl_xor_sync(~0u, rs1, 2);
        rs2 += __shfl_xor_sync(~0u, rs2, 1); rs2 += __shfl_xor_sync(~0u, rs2, 2);
        rs3 += __shfl_xor_sync(~0u, rs3, 1); rs3 += __shfl_xor_sync(~0u, rs3, 2);
        if ((lane & 3) == 0) {             // unique (grp,row) per lane -> plain add
            rsum[grp * 128 + er_]      += rs0;
            rsum[grp * 128 + er_ + 8]  += rs1;
            rsum[grp * 128 + er_ + 16] += rs2;
            rsum[grp * 128 + er_ + 24] += rs3;
        }
        __syncthreads();
    }
    if (tid < 128) rowsum_g[prow + tid] = rsum[tid] + rsum[128 + tid];
}

// ------ q/k/v projection, z-indexed single launch -------------------------
__global__ __launch_bounds__(256)
void proj_qkv_mma(const __nv_bfloat16* xqh, const __nv_bfloat16* xql,
                  const __nv_bfloat16* xkh, const __nv_bfloat16* xkl,
                  const __nv_bfloat16* xvh, const __nv_bfloat16* xvl,
                  const __nv_bfloat16* wqh, const __nv_bfloat16* wql,
                  const __nv_bfloat16* wkh, const __nv_bfloat16* wkl,
                  const __nv_bfloat16* wvh, const __nv_bfloat16* wvl,
                  const float* bq, const float* bk, const float* bv,
                  __nv_bfloat16* qh, __nv_bfloat16* ql, __nv_bfloat16* kh,
                  __nv_bfloat16* kl, __nv_bfloat16* vh, __nv_bfloat16* vl) {
    int z = blockIdx.z;
    const __nv_bfloat16* xh = z == 0 ? xqh : z == 1 ? xkh : xvh;
    const __nv_bfloat16* xl = z == 0 ? xql : z == 1 ? xkl : xvl;
    const __nv_bfloat16* wh = z == 0 ? wqh : z == 1 ? wkh : wvh;
    const __nv_bfloat16* wl = z == 0 ? wql : z == 1 ? wkl : wvl;
    const float* bias = z == 0 ? bq : z == 1 ? bk : bv;
    __nv_bfloat16* oh = z == 0 ? qh : z == 1 ? kh : vh;
    __nv_bfloat16* ol = z == 0 ? ql : z == 1 ? kl : vl;

    int n0 = blockIdx.x << 7, m0 = blockIdx.y << 7;
    float acc[2][8][4] = {};
    mma_core_128(acc, xh + (size_t)m0 * Dd, xl + (size_t)m0 * Dd, Dd,
                 wh + (size_t)n0 * Dd, wl + (size_t)n0 * Dd, Dd, 8);
    int lane = threadIdx.x & 31, wid = threadIdx.x >> 5;
    int er = ((wid & 3) << 5) + (lane >> 2);
    int ec = ((wid >> 2) << 6) + ((lane & 3) << 1);
    #pragma unroll
    for (int mi = 0; mi < 2; mi++)
        #pragma unroll
        for (int j = 0; j < 8; j++) {
            int c = n0 + ec + j * 8;
            float b0 = bias[c], b1 = bias[c + 1];
            #pragma unroll
            for (int hf = 0; hf < 2; hf++) {
                int m = m0 + er + mi * 16 + hf * 8;
                float v0 = acc[mi][j][hf*2] + b0, v1 = acc[mi][j][hf*2+1] + b1;
                int b = m >> 10, s = m & 1023, h = c >> 6, d = c & 63;
                size_t off = ((size_t)((((b << 3) | h) << 10) | s)) * DH + d;
                float r0, r1;
                uint32_t hv = pack_split(v0, v1, r0, r1);
                *reinterpret_cast<uint32_t*>(&oh[off]) = hv;
                *reinterpret_cast<uint32_t*>(&ol[off]) = pack_bf2(r0, r1);
            }
        }
}

// ------ output projection ------------------------------------------------
__global__ __launch_bounds__(256)
void outproj_mma(const __nv_bfloat16* xh, const __nv_bfloat16* xl,
                 const __nv_bfloat16* wh, const __nv_bfloat16* wl,
                 const float* bias, float* __restrict__ out) {
    int n0 = blockIdx.x << 7, m0 = blockIdx.y << 7;
    float acc[2][8][4] = {};
    mma_core_128(acc, xh + (size_t)m0 * Dd, xl + (size_t)m0 * Dd, Dd,
                 wh + (size_t)n0 * Dd, wl + (size_t)n0 * Dd, Dd, 8);
    int lane = threadIdx.x & 31, wid = threadIdx.x >> 5;
    int er = ((wid & 3) << 5) + (lane >> 2);
    int ec = ((wid >> 2) << 6) + ((lane & 3) << 1);
    #pragma unroll
    for (int mi = 0; mi < 2; mi++)
        #pragma unroll
        for (int j = 0; j < 8; j++) {
            int c = n0 + ec + j * 8;
            float b0 = bias[c], b1 = bias[c + 1];
            int m = m0 + er + mi * 16;
            *reinterpret_cast<float2*>(&out[(size_t)m * Dd + c]) =
                make_float2(acc[mi][j][0] + b0, acc[mi][j][1] + b1);
            *reinterpret_cast<float2*>(&out[(size_t)(m + 8) * Dd + c]) =
                make_float2(acc[mi][j][2] + b0, acc[mi][j][3] + b1);
        }
}

// ---------------- rel projection ------------------------------------------
__global__ __launch_bounds__(256)
void rel_proj_kernel(const float* P, const float* Wp, const float* bp,
                     __nv_bfloat16* oh, __nv_bfloat16* ol) {
    __shared__ float sWT[64 * 64];
    __shared__ float sP[4][64];
    int tid = threadIdx.x;
    for (int i = tid; i < 4096; i += 256) sWT[(i & 63) * 64 + (i >> 6)] = Wp[i];
    int g = tid >> 6, d = tid & 63;
    int r = blockIdx.x * 4 + g;
    sP[g][d] = (r < RR) ? P[r * 64 + d] : 0.f;
    __syncthreads();
    float acc = bp[d];
    #pragma unroll 16
    for (int c = 0; c < 64; c++) acc += sP[g][c] * sWT[c * 64 + d];
    if (r < RR) {
        __nv_bfloat16 h = __float2bfloat16_rn(acc);
        oh[r * 64 + d] = h;
        ol[r * 64 + d] = __float2bfloat16_rn(acc - __bfloat162float(h));
    }
}

// ------ ctx = (e/rowsum) @ v; normalizes e in-flight, rewrites attn -------
__global__ __launch_bounds__(256)
void ctx_mma(float* __restrict__ attn, const __nv_bfloat16* vh, const __nv_bfloat16* vl,
             const float* __restrict__ rowsum_g, __nv_bfloat16* ch, __nv_bfloat16* cl) {
    char* sAh = dsm; char* sAl = dsm + 16384;
    const uint32_t sb = smem_u32(dsm);
    __shared__ float sinv[128];
    int bh = blockIdx.y, s0 = blockIdx.x << 7;
    float* ab = attn + ((size_t)bh * Ss + s0) * Ss;
    const __nv_bfloat16* vhb = vh + (size_t)bh * Ss * DH;
    const __nv_bfloat16* vlb = vl + (size_t)bh * Ss * DH;
    int tid = threadIdx.x, lane = tid & 31, wid = tid >> 5;
    int wm = (wid & 3) << 5, wn = (wid >> 2) << 5;

    if (tid < 128) sinv[tid] = 1.0f / rowsum_g[(size_t)bh * Ss + s0 + tid];
    __syncthreads();

    uint32_t a_row = wm + (lane & 15);
    uint32_t a_off = a_row * 128, a_sw = (a_row & 7) << 4, a_cb = lane & 16;
    uint32_t bt = (lane & 7) + (lane & 8);
    uint32_t b_cb16 = lane & 16;

    float acc[2][4][4] = {};
    for (int kc = 0; kc < 16; kc++) {
        if (kc) __syncthreads();
        #pragma unroll
        for (int l = 0; l < 2; l++) {
            int i = tid + l * 256, r = i >> 3, c = i & 7;
            uint32_t doff = r * 128 + ((c * 16) ^ ((r & 7) << 4));
            size_t g = (size_t)(kc * 64 + r) * DH + c * 8;
            cp16(sb + 32768 + doff, vhb + g);
            cp16(sb + 40960 + doff, vlb + g);
        }
        CP_COMMIT();
        #pragma unroll
        for (int l = 0; l < 8; l++) {
            int i = tid + l * 256, r = i >> 4, c = i & 15;
            float iv = sinv[r];
            float* gp = ab + (size_t)r * Ss + kc * 64 + c * 4;
            float4 v = *reinterpret_cast<const float4*>(gp);
            v.x *= iv; v.y *= iv; v.z *= iv; v.w *= iv;
            *reinterpret_cast<float4*>(gp) = v;       // normalized attn
            float r0, r1, r2, r3;
            uint32_t h0 = pack_split(v.x, v.y, r0, r1);
            uint32_t h1 = pack_split(v.z, v.w, r2, r3);
            uint32_t doff = r * 128 + ((c * 8) ^ ((r & 7) << 4));
            *reinterpret_cast<uint2*>(sAh + doff) = make_uint2(h0, h1);
            *reinterpret_cast<uint2*>(sAl + doff) = make_uint2(pack_bf2(r0, r1), pack_bf2(r2, r3));
        }
        CP_WAIT(0);
        __syncthreads();
        #pragma unroll
        for (int k = 0; k < 4; k++) {
            uint32_t aA = sb + a_off + (((uint32_t)(k * 32) + a_cb) ^ a_sw);
            uint32_t ah0[4], ah1[4], al0[4], al1[4];
            ldsm4(ah0, aA); ldsm4(ah1, aA + 2048);
            ldsm4(al0, aA + 16384); ldsm4(al1, aA + 16384 + 2048);
            uint32_t t = (uint32_t)(k * 16) + bt;
            uint32_t vhf[2][4], vlf[2][4];
            #pragma unroll
            for (int l2 = 0; l2 < 2; l2++) {
                uint32_t cb = (uint32_t)((wn + l2 * 16) * 2) + b_cb16;
                uint32_t ba = sb + 32768 + t * 128 + (cb ^ ((t & 7) << 4));
                ldsm4t(vhf[l2], ba);
                ldsm4t(vlf[l2], ba + 8192);
            }
            #pragma unroll
            for (int j = 0; j < 4; j++) {
                const uint32_t* bh = (j & 1) ? &vhf[j >> 1][2] : &vhf[j >> 1][0];
                const uint32_t* bl = (j & 1) ? &vlf[j >> 1][2] : &vlf[j >> 1][0];
                mma16816(acc[0][j], ah0, bh); mma16816(acc[1][j], ah1, bh);
                mma16816(acc[0][j], ah0, bl); mma16816(acc[1][j], ah1, bl);
                mma16816(acc[0][j], al0, bh); mma16816(acc[1][j], al1, bh);
            }
        }
    }
    int b = bh >> 3, h = bh & 7;
    int er = wm + (lane >> 2), ec = wn + ((lane & 3) << 1);
    #pragma unroll
    for (int mi = 0; mi < 2; mi++)
        #pragma unroll
        for (int j = 0; j < 4; j++)
            #pragma unroll
            for (int hf = 0; hf < 2; hf++) {
                int s = s0 + er + mi * 16 + hf * 8;
                int d = ec + j * 8;
                size_t off = ((size_t)((b << 10) | s)) * Dd + (h << 6) + d;
                float r0, r1;
                uint32_t hv = pack_split(acc[mi][j][hf*2], acc[mi][j][hf*2+1], r0, r1);
                *reinterpret_cast<uint32_t*>(&ch[off]) = hv;
                *reinterpret_cast<uint32_t*>(&cl[off]) = pack_bf2(r0, r1);
            }
}

// -------------------------------------------------------------------------
extern "C" void kernel_launch(void* const* d_in, const int* in_sizes, int n_in,
                              void* d_out, int out_size) {
    const float* query   = (const float*)d_in[0];
    const float* key     = (const float*)d_in[1];
    const float* value   = (const float*)d_in[2];
    const float* pos_emb = (const float*)d_in[3];
    const float *Wq = (const float*)d_in[4],  *bq = (const float*)d_in[5];
    const float *Wk = (const float*)d_in[6],  *bk = (const float*)d_in[7];
    const float *Wv = (const float*)d_in[8],  *bv = (const float*)d_in[9];
    const float *Wo = (const float*)d_in[10], *bo = (const float*)d_in[11];
    const float *Wp = (const float*)d_in[12], *bp = (const float*)d_in[13];

    float* out  = (float*)d_out;
    float* attn = out  + (size_t)Bb * Ss * Dd;
    float* csc  = attn + (size_t)Bb * Hh * Ss * Ss;
    float* psc  = csc  + (size_t)Bb * Hh * Ss * Ss;

    __nv_bfloat16 *inqh, *inql, *inkh, *inkl, *invh, *invl;
    __nv_bfloat16 *wqh, *wql, *wkh, *wkl, *wvh, *wvl, *woh, *wol;
    __nv_bfloat16 *qh, *ql, *kh, *kl, *vh, *vl, *relh, *rell, *ctxh, *ctxl;
    float* rowsum;
    cudaGetSymbolAddress((void**)&inqh, g_inqh); cudaGetSymbolAddress((void**)&inql, g_inql);
    cudaGetSymbolAddress((void**)&inkh, g_inkh); cudaGetSymbolAddress((void**)&inkl, g_inkl);
    cudaGetSymbolAddress((void**)&invh, g_invh); cudaGetSymbolAddress((void**)&invl, g_invl);
    cudaGetSymbolAddress((void**)&wqh, g_wqh);   cudaGetSymbolAddress((void**)&wql, g_wql);
    cudaGetSymbolAddress((void**)&wkh, g_wkh);   cudaGetSymbolAddress((void**)&wkl, g_wkl);
    cudaGetSymbolAddress((void**)&wvh, g_wvh);   cudaGetSymbolAddress((void**)&wvl, g_wvl);
    cudaGetSymbolAddress((void**)&woh, g_woh);   cudaGetSymbolAddress((void**)&wol, g_wol);
    cudaGetSymbolAddress((void**)&qh, g_qh);     cudaGetSymbolAddress((void**)&ql, g_ql);
    cudaGetSymbolAddress((void**)&kh, g_kh);     cudaGetSymbolAddress((void**)&kl, g_kl);
    cudaGetSymbolAddress((void**)&vh, g_vh);     cudaGetSymbolAddress((void**)&vl, g_vl);
    cudaGetSymbolAddress((void**)&relh, g_relh); cudaGetSymbolAddress((void**)&rell, g_rell);
    cudaGetSymbolAddress((void**)&ctxh, g_ctxh); cudaGetSymbolAddress((void**)&ctxl, g_ctxl);
    cudaGetSymbolAddress((void**)&rowsum, g_rowsum);

    cudaFuncSetAttribute(proj_qkv_mma, cudaFuncAttributeMaxDynamicSharedMemorySize, 131072);
    cudaFuncSetAttribute(outproj_mma,  cudaFuncAttributeMaxDynamicSharedMemorySize, 131072);
    cudaFuncSetAttribute(scores_fused, cudaFuncAttributeMaxDynamicSharedMemorySize, SMEM_SCORES);
    cudaFuncSetAttribute(ctx_mma,      cudaFuncAttributeMaxDynamicSharedMemorySize, 49152);

    split_all<<<7168, 256>>>(query, key, value, Wq, Wk, Wv, Wo,
        inqh, inql, inkh, inkl, invh, invl,
        wqh, wql, wkh, wkl, wvh, wvl, woh, wol);
    rel_proj_kernel<<<512, 256>>>(pos_emb, Wp, bp, relh, rell);

    proj_qkv_mma<<<dim3(4, 32, 3), 256, 131072>>>(inqh, inql, inkh, inkl, invh, invl,
        wqh, wql, wkh, wkl, wvh, wvl, bq, bk, bv, qh, ql, kh, kl, vh, vl);

    scores_fused<<<dim3(8, 32), 256, SMEM_SCORES>>>(qh, ql, kh, kl, relh, rell,
                                                    csc, psc, attn, rowsum);
    ctx_mma<<<dim3(8, 32), 256, 49152>>>(attn, vh, vl, rowsum, ctxh, ctxl);
    outproj_mma<<<dim3(4, 32), 256, 131072>>>(ctxh, ctxl, woh, wol, bo, out);
}